// round 8
// baseline (speedup 1.0000x reference)
#include <cuda_runtime.h>
#include <cuda_bf16.h>
#include <math.h>
#include <stdint.h>

// ---------------- problem constants ----------------
#define BATCH   2
#define LSEQ    1024
#define DMODEL  512
#define DINNER  1024
#define DSTATE  64
#define DTRANK  32
#define ROWS    (BATCH*LSEQ)          // 2048
#define EPSV    1e-6f

// ---------------- scratch (device globals; no allocations allowed) ----------------
__device__ __align__(16) __nv_bfloat16 g_h_b   [ROWS*DMODEL];      // rmsnorm(x) bf16
__device__ __align__(16) float         g_xz    [ROWS*2*DINNER];    // h @ W_in^T (u | z) fp32
__device__ __align__(16) __nv_bfloat16 g_u_b   [2][ROWS*DINNER];   // conv+silu bf16
__device__ __align__(16) float         g_xdbl  [2][ROWS*128];      // [B|C] fp32 (128 cols)
__device__ __align__(16) float         g_dt    [2][ROWS*DINNER];   // softplus(dt) fp32
__device__ __align__(16) __nv_bfloat16 g_gate_b[2][ROWS*DINNER];   // (y+u*D)*silu(z) bf16
__device__ __align__(16) __nv_bfloat16 g_hcat_b[ROWS*2*DMODEL];    // [hf|hb] bf16
__device__ __align__(16) float         g_uv    [ROWS*2*DMODEL];    // fuse out fp32
__device__ __align__(16) __nv_bfloat16 g_h2_b  [ROWS*DMODEL];      // silu(glu) bf16
__device__ __align__(16) __nv_bfloat16 g_ff1_b [ROWS*4*DMODEL];    // silu(ff1) bf16
__device__ __align__(16) float         g_ff2   [ROWS*DMODEL];      // ff2 fp32
// bf16 weights
__device__ __align__(16) __nv_bfloat16 g_Win_b [2*DINNER*DMODEL];
__device__ __align__(16) __nv_bfloat16 g_Wcat_b[(DINNER+128)*DINNER]; // [Wcomb(1024) | Wxp(128)] rows
__device__ __align__(16) __nv_bfloat16 g_Wout_b[DMODEL*DINNER];
__device__ __align__(16) __nv_bfloat16 g_fuse_b[2*DMODEL*2*DMODEL];
__device__ __align__(16) __nv_bfloat16 g_ff1w_b[4*DMODEL*DMODEL];
__device__ __align__(16) __nv_bfloat16 g_ff2w_b[DMODEL*4*DMODEL];

// ---------------- math helpers ----------------
__device__ __forceinline__ float sigmoidf_(float x){ return 1.0f/(1.0f+expf(-x)); }
__device__ __forceinline__ float siluf_(float x){ return x/(1.0f+expf(-x)); }
__device__ __forceinline__ float softplusf_(float x){ return (x>20.0f)? x : log1pf(expf(x)); }

__device__ __forceinline__ uint32_t smem_u32_(const void* p){
    uint32_t a;
    asm("{ .reg .u64 t; cvta.to.shared.u64 t, %1; cvt.u32.u64 %0, t; }" : "=r"(a) : "l"(p));
    return a;
}

// ---------------- mma.sync bf16 GEMM: C[M,N] = A[M,K](bf16) @ W[N,K](bf16)^T ----------------
// 128x128 CTA tile, 8 warps (2 x 4), warp tile 64x32.
// K chunk = 64, 3-stage cp.async pipeline, one __syncthreads per chunk.
// smem rows padded to 72 bf16 (144B).
// EPI: 0 none, 1 silu, 3 +bias, 4 split(dt: softplus+bias | BC: none -> C2)
#define KCHUNK  64
#define SROW    72
#define CHUNK_BYTES (128*SROW*2)          // 18432 per matrix per stage
#define NSTAGE  3
#define GEMM_SMEM (NSTAGE*2*CHUNK_BYTES)  // 110592

__device__ __forceinline__ void ldsm_x4(uint32_t& r0, uint32_t& r1, uint32_t& r2, uint32_t& r3, uint32_t a){
    asm volatile("ldmatrix.sync.aligned.m8n8.x4.shared.b16 {%0,%1,%2,%3},[%4];"
                 : "=r"(r0),"=r"(r1),"=r"(r2),"=r"(r3) : "r"(a));
}
__device__ __forceinline__ void ldsm_x2(uint32_t& r0, uint32_t& r1, uint32_t a){
    asm volatile("ldmatrix.sync.aligned.m8n8.x2.shared.b16 {%0,%1},[%2];"
                 : "=r"(r0),"=r"(r1) : "r"(a));
}
__device__ __forceinline__ void mma16816(float* d, const uint32_t* a, const uint32_t* b){
    asm volatile("mma.sync.aligned.m16n8k16.row.col.f32.bf16.bf16.f32 "
                 "{%0,%1,%2,%3},{%4,%5,%6,%7},{%8,%9},{%0,%1,%2,%3};"
                 : "+f"(d[0]),"+f"(d[1]),"+f"(d[2]),"+f"(d[3])
                 : "r"(a[0]),"r"(a[1]),"r"(a[2]),"r"(a[3]), "r"(b[0]),"r"(b[1]));
}

template<int EPI, typename OutT>
__global__ void __launch_bounds__(256, 2)
tc_gemm(const __nv_bfloat16* __restrict__ A,
        const __nv_bfloat16* __restrict__ W,
        const float* __restrict__ bias,
        OutT* __restrict__ C, int ldc, int K,
        size_t zsA, size_t zsC,
        float* __restrict__ C2, size_t zsC2)
{
    extern __shared__ char smem[];
    uint32_t sb = smem_u32_(smem);
    int tid = threadIdx.x, lane = tid & 31, w = tid >> 5;
    int wm = w >> 2, wn = w & 3;              // 2 x 4 warp grid
    int m0 = blockIdx.y*128, n0 = blockIdx.x*128;

    A += (size_t)blockIdx.z * zsA;
    C += (size_t)blockIdx.z * zsC;
    if (EPI==4) C2 += (size_t)blockIdx.z * zsC2;

    const __nv_bfloat16* Abase = A + (size_t)m0*K;
    const __nv_bfloat16* Wbase = W + (size_t)n0*K;
    const int NC = K / KCHUNK;

    auto load_chunk = [&](int c, int s){
        uint32_t abuf = sb + (uint32_t)s*2*CHUNK_BYTES;
        uint32_t bbuf = abuf + CHUNK_BYTES;
        const __nv_bfloat16* Ag = Abase + c*KCHUNK;
        const __nv_bfloat16* Wg = Wbase + c*KCHUNK;
        #pragma unroll
        for (int i=0;i<4;i++){
            int idx = i*256 + tid;            // 0..1023
            int r = idx>>3, cc = idx&7;
            uint32_t dst = (uint32_t)(r*(SROW*2) + cc*16);
            asm volatile("cp.async.cg.shared.global [%0],[%1],16;"
                         :: "r"(abuf+dst), "l"((const void*)(Ag + (size_t)r*K + cc*8)));
            asm volatile("cp.async.cg.shared.global [%0],[%1],16;"
                         :: "r"(bbuf+dst), "l"((const void*)(Wg + (size_t)r*K + cc*8)));
        }
        asm volatile("cp.async.commit_group;");
    };

    float acc[4][4][4];
    #pragma unroll
    for (int i=0;i<4;i++)
        #pragma unroll
        for (int j=0;j<4;j++)
            #pragma unroll
            for (int q=0;q<4;q++) acc[i][j][q]=0.f;

    int a_row  = wm*64 + (lane & 15);
    int a_koff = (lane >> 4) * 8;
    int b_row  = wn*32 + (lane & 7);
    int b_koff = ((lane >> 3) & 1) * 8;

    load_chunk(0,0);
    if (NC>1) load_chunk(1,1);

    for (int c=0;c<NC;c++){
        int s = c % NSTAGE;
        if (c+1<NC) asm volatile("cp.async.wait_group 1;" ::: "memory");
        else        asm volatile("cp.async.wait_group 0;" ::: "memory");
        __syncthreads();
        if (c+2<NC) load_chunk(c+2, (c+2)%NSTAGE);
        uint32_t abuf = sb + (uint32_t)s*2*CHUNK_BYTES;
        uint32_t bbuf = abuf + CHUNK_BYTES;
        #pragma unroll
        for (int ks=0; ks<KCHUNK/16; ks++){
            uint32_t afr[4][4], bfr[4][2];
            #pragma unroll
            for (int mt=0;mt<4;mt++){
                uint32_t addr = abuf + (uint32_t)(((a_row + mt*16)*SROW + ks*16 + a_koff)*2);
                ldsm_x4(afr[mt][0],afr[mt][1],afr[mt][2],afr[mt][3], addr);
            }
            #pragma unroll
            for (int nt=0;nt<4;nt++){
                uint32_t addr = bbuf + (uint32_t)(((b_row + nt*8)*SROW + ks*16 + b_koff)*2);
                ldsm_x2(bfr[nt][0],bfr[nt][1], addr);
            }
            #pragma unroll
            for (int mt=0;mt<4;mt++)
                #pragma unroll
                for (int nt=0;nt<4;nt++)
                    mma16816(acc[mt][nt], afr[mt], bfr[nt]);
        }
    }

    // epilogue
    bool bc_side = (EPI==4) && (n0 >= DINNER);  // BC columns -> C2
    float* Cf = bc_side ? C2 : (float*)C;       // only used when OutT==float
    int ldout = bc_side ? 128 : ldc;
    int colShift = bc_side ? DINNER : 0;

    int rbase = m0 + wm*64 + (lane>>2);
    int cbase = n0 + wn*32 + (lane&3)*2;
    #pragma unroll
    for (int mt=0;mt<4;mt++){
        #pragma unroll
        for (int nt=0;nt<4;nt++){
            int col = cbase + nt*8;
            float v[4];
            #pragma unroll
            for (int q=0;q<4;q++){
                float x = acc[mt][nt][q];
                int cc = col + (q&1);
                if (EPI==1) x = siluf_(x);
                else if (EPI==3) x = x + bias[cc];
                else if (EPI==4){ if (!bc_side) x = softplusf_(x + bias[cc]); }
                v[q] = x;
            }
            int r0 = rbase + mt*16, r1 = r0 + 8;
            if (sizeof(OutT)==4){
                int oc = col - colShift;
                *(float2*)(Cf + (size_t)r0*ldout + oc) = make_float2(v[0],v[1]);
                *(float2*)(Cf + (size_t)r1*ldout + oc) = make_float2(v[2],v[3]);
            } else {
                *(__nv_bfloat162*)((__nv_bfloat16*)C + (size_t)r0*ldc + col) = __floats2bfloat162_rn(v[0],v[1]);
                *(__nv_bfloat162*)((__nv_bfloat16*)C + (size_t)r1*ldc + col) = __floats2bfloat162_rn(v[2],v[3]);
            }
        }
    }
}

// ---------------- rmsnorm ----------------
template<typename OutT>
__global__ void rmsnorm_kernel(const float* __restrict__ x,
                               const float* __restrict__ addsrc,
                               const float* __restrict__ w,
                               OutT* __restrict__ out)
{
    int row = blockIdx.x;
    int t = threadIdx.x;
    const float4* x4 = (const float4*)(x + (size_t)row*DMODEL);
    float4 v = x4[t];
    if (addsrc){
        const float4* a4 = (const float4*)(addsrc + (size_t)row*DMODEL);
        float4 a = a4[t];
        v.x+=a.x; v.y+=a.y; v.z+=a.z; v.w+=a.w;
    }
    float ss = v.x*v.x + v.y*v.y + v.z*v.z + v.w*v.w;
    #pragma unroll
    for (int o=16;o;o>>=1) ss += __shfl_xor_sync(0xffffffffu, ss, o);
    __shared__ float sacc[4];
    if ((t&31)==0) sacc[t>>5] = ss;
    __syncthreads();
    float tot = sacc[0]+sacc[1]+sacc[2]+sacc[3];
    float rinv = rsqrtf(tot*(1.0f/(float)DMODEL) + EPSV);
    const float4* w4 = (const float4*)w;
    float4 wv = w4[t];
    float o0=v.x*rinv*wv.x, o1=v.y*rinv*wv.y, o2=v.z*rinv*wv.z, o3=v.w*rinv*wv.w;
    OutT* op = out + (size_t)row*DMODEL + t*4;
    op[0]=(OutT)o0; op[1]=(OutT)o1; op[2]=(OutT)o2; op[3]=(OutT)o3;
}

// ---------------- single-kernel weight conversion (vectorized) ----------------
#define NV_WIN  (2*DINNER*DMODEL/4)     // 262144
#define NV_WXP  (128*DINNER/4)          // 32768
#define NV_WOUT (DMODEL*DINNER/4)       // 131072
#define NV_FUSE (4*DMODEL*DMODEL/4)     // 262144
#define NV_TOT  (NV_WIN+NV_WXP+NV_WOUT+3*NV_FUSE)

__device__ __forceinline__ void cvt4(const float* s, __nv_bfloat16* d, int i){
    float4 v = ((const float4*)s)[i];
    ((__nv_bfloat162*)d)[2*i  ] = __floats2bfloat162_rn(v.x, v.y);
    ((__nv_bfloat162*)d)[2*i+1] = __floats2bfloat162_rn(v.z, v.w);
}
__global__ void convert_all(const float* __restrict__ W_in,
                            const float* __restrict__ W_xproj,
                            const float* __restrict__ W_out,
                            const float* __restrict__ fuse_W,
                            const float* __restrict__ ff_W1,
                            const float* __restrict__ ff_W2)
{
    int i = blockIdx.x*256 + threadIdx.x;
    if (i >= NV_TOT) return;
    if (i < NV_WIN){ cvt4(W_in, g_Win_b, i); return; }
    i -= NV_WIN;
    if (i < NV_WXP){ cvt4(W_xproj + DTRANK*DINNER, g_Wcat_b + DINNER*DINNER, i); return; }
    i -= NV_WXP;
    if (i < NV_WOUT){ cvt4(W_out, g_Wout_b, i); return; }
    i -= NV_WOUT;
    if (i < NV_FUSE){ cvt4(fuse_W, g_fuse_b, i); return; }
    i -= NV_FUSE;
    if (i < NV_FUSE){ cvt4(ff_W1, g_ff1w_b, i); return; }
    i -= NV_FUSE;
    cvt4(ff_W2, g_ff2w_b, i);
}

// W_comb = W_dt[1024,32] @ W_xproj[:32, 1024] -> rows 0..1023 of W_cat
__global__ void wcomb_kernel(const float* __restrict__ W_dt, const float* __restrict__ W_xproj)
{
    int idx = blockIdx.x*256 + threadIdx.x;   // over 1024*1024
    int i = idx >> 10, j = idx & 1023;
    float s = 0.f;
    #pragma unroll
    for (int r=0;r<32;r++) s = fmaf(W_dt[i*32+r], W_xproj[r*DINNER + j], s);
    g_Wcat_b[idx] = __float2bfloat16(s);
}

// ---------------- depthwise causal conv (both directions) + bias + silu -> bf16 ----------------
__global__ void conv_kernel(const float* __restrict__ cw, const float* __restrict__ cb)
{
    int idx = blockIdx.x*256 + threadIdx.x;
    if (idx >= ROWS*DINNER) return;
    int d = idx & (DINNER-1);
    int r = idx >> 10;
    int l = r & (LSEQ-1);
    int b = r >> 10;
    float w0=cw[d*4+0], w1=cw[d*4+1], w2=cw[d*4+2], w3=cw[d*4+3];
    float bias = cb[d];
    const float* up = g_xz + (size_t)(b<<10)*(2*DINNER) + d;
    auto U = [&](int li)->float{ return (li>=0 && li<LSEQ) ? up[(size_t)li*(2*DINNER)] : 0.0f; };
    float um3=U(l-3), um2=U(l-2), um1=U(l-1), u0=U(l), up1=U(l+1), up2=U(l+2), up3=U(l+3);
    float f  = bias + w0*um3 + w1*um2 + w2*um1 + w3*u0;
    float bw = bias + w3*u0  + w2*up1 + w1*up2 + w0*up3;
    g_u_b[0][idx] = __float2bfloat16(siluf_(f));
    g_u_b[1][idx] = __float2bfloat16(siluf_(bw));
}

// ---------------- selective scan: one warp per (dir, b, d); prefetched + unrolled ----------------
__global__ void __launch_bounds__(128)
scan_kernel(const float* __restrict__ A_log, const float* __restrict__ Dskip)
{
    int w    = (blockIdx.x*blockDim.x + threadIdx.x) >> 5;
    int lane = threadIdx.x & 31;
    int dir  = w >> 11;
    int rem  = w & 2047;
    int b    = rem >> 10;
    int d    = rem & 1023;

    int n0 = lane*2;
    float a0 = -expf(A_log[d*DSTATE + n0]);
    float a1 = -expf(A_log[d*DSTATE + n0 + 1]);
    float dsk = Dskip[d];
    float s0 = 0.f, s1 = 0.f;

    int l0 = dir ? (LSEQ-1) : 0;
    intptr_t stp = dir ? -1 : 1;
    size_t r0 = (size_t)(b<<10) + l0;

    const float* dtP = g_dt[dir] + r0*DINNER + d;
    const __nv_bfloat16* uP = g_u_b[dir] + r0*DINNER + d;
    const float* bP  = g_xdbl[dir] + r0*128 + n0;
    const float* zP  = g_xz + r0*(2*DINNER) + DINNER + d;
    __nv_bfloat16* gP = g_gate_b[dir] + r0*DINNER + d;

    intptr_t sD = stp*DINNER, s128 = stp*128, s2D = stp*(2*DINNER);

    // prefetch step 0
    float dt_c = __ldg(dtP);
    float uu_c = __bfloat162float(*uP);
    float2 B_c = *(const float2*)bP;
    float2 C_c = *(const float2*)(bP + 64);
    float z_c  = *zP;

    #pragma unroll 4
    for (int t=0; t<LSEQ; t++){
        dtP += sD; uP += sD; bP += s128; zP += s2D;
        // prefetch step t+1 (issues before the reduce chain of step t)
        float dt_n = 0.f, uu_n = 0.f, z_n = 0.f;
        float2 B_n = make_float2(0.f,0.f), C_n = make_float2(0.f,0.f);
        if (t+1 < LSEQ){
            dt_n = __ldg(dtP);
            uu_n = __bfloat162float(*uP);
            B_n  = *(const float2*)bP;
            C_n  = *(const float2*)(bP + 64);
            z_n  = *zP;
        }
        // step t math
        float dA0 = __expf(dt_c*a0);
        float dA1 = __expf(dt_c*a1);
        float dtu = dt_c*uu_c;
        s0 = fmaf(s0, dA0, dtu*B_c.x);
        s1 = fmaf(s1, dA1, dtu*B_c.y);
        float p = s0*C_c.x + s1*C_c.y;
        #pragma unroll
        for (int o=16;o;o>>=1) p += __shfl_xor_sync(0xffffffffu, p, o);
        if (lane==0){
            float y = p + uu_c*dsk;
            *gP = __float2bfloat16(y * (z_c/(1.0f+__expf(-z_c))));
        }
        gP += sD;
        dt_c = dt_n; uu_c = uu_n; B_c = B_n; C_c = C_n; z_c = z_n;
    }
}

// ---------------- GLU gate + silu -> bf16 ----------------
__global__ void glu_kernel()
{
    int idx = blockIdx.x*256 + threadIdx.x;
    if (idx >= ROWS*DMODEL) return;
    int r = idx >> 9;
    int d = idx & (DMODEL-1);
    float ug = g_uv[(size_t)r*(2*DMODEL) + d];
    float vg = g_uv[(size_t)r*(2*DMODEL) + DMODEL + d];
    float h  = ug * sigmoidf_(vg);
    g_h2_b[idx] = __float2bfloat16(siluf_(h));
}

// ---------------- host side ----------------
template<typename T>
static T* sym_addr(const void* sym)
{
    void* p = nullptr;
    cudaGetSymbolAddress(&p, sym);
    return (T*)p;
}

extern "C" void kernel_launch(void* const* d_in, const int* in_sizes, int n_in,
                              void* d_out, int out_size)
{
    const float* x       = (const float*)d_in[0];
    const float* W_in    = (const float*)d_in[1];
    const float* conv_w  = (const float*)d_in[2];
    const float* conv_b  = (const float*)d_in[3];
    const float* W_xproj = (const float*)d_in[4];
    const float* W_dt    = (const float*)d_in[5];
    const float* b_dt    = (const float*)d_in[6];
    const float* A_log   = (const float*)d_in[7];
    const float* Dskip   = (const float*)d_in[8];
    const float* W_out   = (const float*)d_in[9];
    const float* nin_w   = (const float*)d_in[10];
    const float* fuse_W  = (const float*)d_in[11];
    const float* fuse_b  = (const float*)d_in[12];
    const float* ff_W1   = (const float*)d_in[13];
    const float* ff_W2   = (const float*)d_in[14];
    const float* nout_w  = (const float*)d_in[15];
    float* out = (float*)d_out;

    __nv_bfloat16* p_h    = sym_addr<__nv_bfloat16>(g_h_b);
    float*         p_xz   = sym_addr<float>(g_xz);
    __nv_bfloat16* p_u    = sym_addr<__nv_bfloat16>(g_u_b);
    float*         p_xdbl = sym_addr<float>(g_xdbl);
    float*         p_dt   = sym_addr<float>(g_dt);
    __nv_bfloat16* p_gate = sym_addr<__nv_bfloat16>(g_gate_b);
    __nv_bfloat16* p_hcat = sym_addr<__nv_bfloat16>(g_hcat_b);
    float*         p_uv   = sym_addr<float>(g_uv);
    __nv_bfloat16* p_h2   = sym_addr<__nv_bfloat16>(g_h2_b);
    __nv_bfloat16* p_ff1  = sym_addr<__nv_bfloat16>(g_ff1_b);
    float*         p_ff2  = sym_addr<float>(g_ff2);
    __nv_bfloat16* p_Win  = sym_addr<__nv_bfloat16>(g_Win_b);
    __nv_bfloat16* p_Wcat = sym_addr<__nv_bfloat16>(g_Wcat_b);
    __nv_bfloat16* p_Wout = sym_addr<__nv_bfloat16>(g_Wout_b);
    __nv_bfloat16* p_Wfu  = sym_addr<__nv_bfloat16>(g_fuse_b);
    __nv_bfloat16* p_Wf1  = sym_addr<__nv_bfloat16>(g_ff1w_b);
    __nv_bfloat16* p_Wf2  = sym_addr<__nv_bfloat16>(g_ff2w_b);

    cudaFuncSetAttribute(tc_gemm<0,float>,         cudaFuncAttributeMaxDynamicSharedMemorySize, GEMM_SMEM);
    cudaFuncSetAttribute(tc_gemm<4,float>,         cudaFuncAttributeMaxDynamicSharedMemorySize, GEMM_SMEM);
    cudaFuncSetAttribute(tc_gemm<3,float>,         cudaFuncAttributeMaxDynamicSharedMemorySize, GEMM_SMEM);
    cudaFuncSetAttribute(tc_gemm<0,__nv_bfloat16>, cudaFuncAttributeMaxDynamicSharedMemorySize, GEMM_SMEM);
    cudaFuncSetAttribute(tc_gemm<1,__nv_bfloat16>, cudaFuncAttributeMaxDynamicSharedMemorySize, GEMM_SMEM);

    dim3 blk(256);

    // 1. weight conversions (one launch) + combined dt weight
    convert_all<<<(NV_TOT+255)/256, blk>>>(W_in, W_xproj, W_out, fuse_W, ff_W1, ff_W2);
    wcomb_kernel<<<(DINNER*DINNER)/256, blk>>>(W_dt, W_xproj);

    // 2. h = rmsnorm(x) -> bf16
    rmsnorm_kernel<__nv_bfloat16><<<ROWS, 128>>>(x, nullptr, nin_w, p_h);

    // 3. xz = h @ W_in^T   (N=2048, K=512) -> fp32
    tc_gemm<0,float><<<dim3(16,16), blk, GEMM_SMEM>>>(p_h, p_Win, nullptr, p_xz, 2*DINNER, DMODEL,
                                                      0, 0, nullptr, 0);

    // 4. conv + silu, both directions -> bf16
    conv_kernel<<<(ROWS*DINNER)/256, blk>>>(conv_w, conv_b);

    // 5. [dt | BC] = u @ Wcat^T  (N=1152, K=1024), both directions via blockIdx.z
    tc_gemm<4,float><<<dim3(9,16,2), blk, GEMM_SMEM>>>(p_u, p_Wcat, b_dt,
                                                       p_dt, DINNER, DINNER,
                                                       (size_t)ROWS*DINNER, (size_t)ROWS*DINNER,
                                                       p_xdbl, (size_t)ROWS*128);

    // 6. selective scan -> gate bf16
    scan_kernel<<<1024, 128>>>(A_log, Dskip);

    // 7. hcat[:, dir*512:] = gate @ W_out^T (N=512, K=1024), both dirs via z
    tc_gemm<0,__nv_bfloat16><<<dim3(4,16,2), blk, GEMM_SMEM>>>(p_gate, p_Wout, nullptr,
                                                               p_hcat, 2*DMODEL, DINNER,
                                                               (size_t)ROWS*DINNER, (size_t)DMODEL,
                                                               nullptr, 0);

    // 8. uv = hcat @ fuse_W^T + fuse_b  (N=1024, K=1024) -> fp32
    tc_gemm<3,float><<<dim3(8,16), blk, GEMM_SMEM>>>(p_hcat, p_Wfu, fuse_b, p_uv, 2*DMODEL, 2*DMODEL,
                                                     0, 0, nullptr, 0);

    // 9. h2 = silu(ug * sigmoid(vg)) -> bf16
    glu_kernel<<<(ROWS*DMODEL)/256, blk>>>();

    // 10. ff1 = silu(h2 @ ff_W1^T)  (N=2048, K=512) -> bf16
    tc_gemm<1,__nv_bfloat16><<<dim3(16,16), blk, GEMM_SMEM>>>(p_h2, p_Wf1, nullptr, p_ff1, 4*DMODEL, DMODEL,
                                                              0, 0, nullptr, 0);

    // 11. ff2 = ff1 @ ff_W2^T  (N=512, K=2048) -> fp32
    tc_gemm<0,float><<<dim3(4,16), blk, GEMM_SMEM>>>(p_ff1, p_Wf2, nullptr, p_ff2, DMODEL, 4*DMODEL,
                                                     0, 0, nullptr, 0);

    // 12. out = rmsnorm(x + ff2)
    rmsnorm_kernel<float><<<ROWS, 128>>>(x, p_ff2, nout_w, out);
}

// round 11
// speedup vs baseline: 1.4966x; 1.4966x over previous
#include <cuda_runtime.h>
#include <cuda_bf16.h>
#include <math.h>
#include <stdint.h>

// ---------------- problem constants ----------------
#define BATCH   2
#define LSEQ    1024
#define DMODEL  512
#define DINNER  1024
#define DSTATE  64
#define DTRANK  32
#define ROWS    (BATCH*LSEQ)          // 2048
#define EPSV    1e-6f

// ---------------- scratch (device globals; no allocations allowed) ----------------
__device__ __align__(16) __nv_bfloat16 g_h_b   [ROWS*DMODEL];      // rmsnorm(x) bf16
__device__ __align__(16) float         g_xz    [ROWS*2*DINNER];    // h @ W_in^T (u | z) fp32
__device__ __align__(16) __nv_bfloat16 g_u_b   [2][ROWS*DINNER];   // conv+silu bf16
__device__ __align__(16) float         g_xdbl  [2][ROWS*128];      // [B|C] fp32 (128 cols)
__device__ __align__(16) float         g_dt    [2][ROWS*DINNER];   // softplus(dt) fp32
__device__ __align__(16) __nv_bfloat16 g_gate_b[2][ROWS*DINNER];   // (y+u*D)*silu(z) bf16
__device__ __align__(16) __nv_bfloat16 g_hcat_b[ROWS*2*DMODEL];    // [hf|hb] bf16
__device__ __align__(16) float         g_uv    [ROWS*2*DMODEL];    // fuse out fp32
__device__ __align__(16) __nv_bfloat16 g_h2_b  [ROWS*DMODEL];      // silu(glu) bf16
__device__ __align__(16) __nv_bfloat16 g_ff1_b [ROWS*4*DMODEL];    // silu(ff1) bf16
__device__ __align__(16) float         g_ff2   [ROWS*DMODEL];      // ff2 fp32
// bf16 weights
__device__ __align__(16) __nv_bfloat16 g_Win_b [2*DINNER*DMODEL];
__device__ __align__(16) __nv_bfloat16 g_Wcat_b[(DINNER+128)*DINNER]; // [Wcomb(1024) | Wxp(128)] rows
__device__ __align__(16) __nv_bfloat16 g_Wout_b[DMODEL*DINNER];
__device__ __align__(16) __nv_bfloat16 g_fuse_b[2*DMODEL*2*DMODEL];
__device__ __align__(16) __nv_bfloat16 g_ff1w_b[4*DMODEL*DMODEL];
__device__ __align__(16) __nv_bfloat16 g_ff2w_b[DMODEL*4*DMODEL];

// ---------------- math helpers ----------------
__device__ __forceinline__ float sigmoidf_(float x){ return 1.0f/(1.0f+expf(-x)); }
__device__ __forceinline__ float siluf_(float x){ return x/(1.0f+expf(-x)); }
__device__ __forceinline__ float softplusf_(float x){ return (x>20.0f)? x : log1pf(expf(x)); }

__device__ __forceinline__ uint32_t smem_u32_(const void* p){
    uint32_t a;
    asm("{ .reg .u64 t; cvta.to.shared.u64 t, %1; cvt.u32.u64 %0, t; }" : "=r"(a) : "l"(p));
    return a;
}

// ---------------- mma.sync bf16 GEMM: C[M,N] = A[M,K](bf16) @ W[N,K](bf16)^T ----------------
// 128x128 CTA tile, 8 warps (2 x 4), warp tile 64x32.
// K chunk = 64, 3-stage cp.async pipeline, one __syncthreads per chunk.
// smem rows padded to 72 bf16 (144B).
// EPI: 0 none, 1 silu, 3 +bias, 4 split(dt: softplus+bias | BC: none -> C2)
#define KCHUNK  64
#define SROW    72
#define CHUNK_BYTES (128*SROW*2)          // 18432 per matrix per stage
#define NSTAGE  3
#define GEMM_SMEM (NSTAGE*2*CHUNK_BYTES)  // 110592

__device__ __forceinline__ void ldsm_x4(uint32_t& r0, uint32_t& r1, uint32_t& r2, uint32_t& r3, uint32_t a){
    asm volatile("ldmatrix.sync.aligned.m8n8.x4.shared.b16 {%0,%1,%2,%3},[%4];"
                 : "=r"(r0),"=r"(r1),"=r"(r2),"=r"(r3) : "r"(a));
}
__device__ __forceinline__ void ldsm_x2(uint32_t& r0, uint32_t& r1, uint32_t a){
    asm volatile("ldmatrix.sync.aligned.m8n8.x2.shared.b16 {%0,%1},[%2];"
                 : "=r"(r0),"=r"(r1) : "r"(a));
}
__device__ __forceinline__ void mma16816(float* d, const uint32_t* a, const uint32_t* b){
    asm volatile("mma.sync.aligned.m16n8k16.row.col.f32.bf16.bf16.f32 "
                 "{%0,%1,%2,%3},{%4,%5,%6,%7},{%8,%9},{%0,%1,%2,%3};"
                 : "+f"(d[0]),"+f"(d[1]),"+f"(d[2]),"+f"(d[3])
                 : "r"(a[0]),"r"(a[1]),"r"(a[2]),"r"(a[3]), "r"(b[0]),"r"(b[1]));
}

template<int EPI, typename OutT>
__global__ void __launch_bounds__(256, 2)
tc_gemm(const __nv_bfloat16* __restrict__ A,
        const __nv_bfloat16* __restrict__ W,
        const float* __restrict__ bias,
        OutT* __restrict__ C, int ldc, int K,
        size_t zsA, size_t zsC,
        float* __restrict__ C2, size_t zsC2)
{
    extern __shared__ char smem[];
    uint32_t sb = smem_u32_(smem);
    int tid = threadIdx.x, lane = tid & 31, w = tid >> 5;
    int wm = w >> 2, wn = w & 3;              // 2 x 4 warp grid
    int m0 = blockIdx.y*128, n0 = blockIdx.x*128;

    A += (size_t)blockIdx.z * zsA;
    C += (size_t)blockIdx.z * zsC;
    if (EPI==4) C2 += (size_t)blockIdx.z * zsC2;

    const __nv_bfloat16* Abase = A + (size_t)m0*K;
    const __nv_bfloat16* Wbase = W + (size_t)n0*K;
    const int NC = K / KCHUNK;

    auto load_chunk = [&](int c, int s){
        uint32_t abuf = sb + (uint32_t)s*2*CHUNK_BYTES;
        uint32_t bbuf = abuf + CHUNK_BYTES;
        const __nv_bfloat16* Ag = Abase + c*KCHUNK;
        const __nv_bfloat16* Wg = Wbase + c*KCHUNK;
        #pragma unroll
        for (int i=0;i<4;i++){
            int idx = i*256 + tid;            // 0..1023
            int r = idx>>3, cc = idx&7;
            uint32_t dst = (uint32_t)(r*(SROW*2) + cc*16);
            asm volatile("cp.async.cg.shared.global [%0],[%1],16;"
                         :: "r"(abuf+dst), "l"((const void*)(Ag + (size_t)r*K + cc*8)));
            asm volatile("cp.async.cg.shared.global [%0],[%1],16;"
                         :: "r"(bbuf+dst), "l"((const void*)(Wg + (size_t)r*K + cc*8)));
        }
        asm volatile("cp.async.commit_group;");
    };

    float acc[4][4][4];
    #pragma unroll
    for (int i=0;i<4;i++)
        #pragma unroll
        for (int j=0;j<4;j++)
            #pragma unroll
            for (int q=0;q<4;q++) acc[i][j][q]=0.f;

    int a_row  = wm*64 + (lane & 15);
    int a_koff = (lane >> 4) * 8;
    int b_row  = wn*32 + (lane & 7);
    int b_koff = ((lane >> 3) & 1) * 8;

    load_chunk(0,0);
    if (NC>1) load_chunk(1,1);

    for (int c=0;c<NC;c++){
        int s = c % NSTAGE;
        if (c+1<NC) asm volatile("cp.async.wait_group 1;" ::: "memory");
        else        asm volatile("cp.async.wait_group 0;" ::: "memory");
        __syncthreads();
        if (c+2<NC) load_chunk(c+2, (c+2)%NSTAGE);
        uint32_t abuf = sb + (uint32_t)s*2*CHUNK_BYTES;
        uint32_t bbuf = abuf + CHUNK_BYTES;
        #pragma unroll
        for (int ks=0; ks<KCHUNK/16; ks++){
            uint32_t afr[4][4], bfr[4][2];
            #pragma unroll
            for (int mt=0;mt<4;mt++){
                uint32_t addr = abuf + (uint32_t)(((a_row + mt*16)*SROW + ks*16 + a_koff)*2);
                ldsm_x4(afr[mt][0],afr[mt][1],afr[mt][2],afr[mt][3], addr);
            }
            #pragma unroll
            for (int nt=0;nt<4;nt++){
                uint32_t addr = bbuf + (uint32_t)(((b_row + nt*8)*SROW + ks*16 + b_koff)*2);
                ldsm_x2(bfr[nt][0],bfr[nt][1], addr);
            }
            #pragma unroll
            for (int mt=0;mt<4;mt++)
                #pragma unroll
                for (int nt=0;nt<4;nt++)
                    mma16816(acc[mt][nt], afr[mt], bfr[nt]);
        }
    }

    // epilogue
    bool bc_side = (EPI==4) && (n0 >= DINNER);  // BC columns -> C2
    float* Cf = bc_side ? C2 : (float*)C;       // only used when OutT==float
    int ldout = bc_side ? 128 : ldc;
    int colShift = bc_side ? DINNER : 0;

    int rbase = m0 + wm*64 + (lane>>2);
    int cbase = n0 + wn*32 + (lane&3)*2;
    #pragma unroll
    for (int mt=0;mt<4;mt++){
        #pragma unroll
        for (int nt=0;nt<4;nt++){
            int col = cbase + nt*8;
            float v[4];
            #pragma unroll
            for (int q=0;q<4;q++){
                float x = acc[mt][nt][q];
                int cc = col + (q&1);
                if (EPI==1) x = siluf_(x);
                else if (EPI==3) x = x + bias[cc];
                else if (EPI==4){ if (!bc_side) x = softplusf_(x + bias[cc]); }
                v[q] = x;
            }
            int r0 = rbase + mt*16, r1 = r0 + 8;
            if (sizeof(OutT)==4){
                int oc = col - colShift;
                *(float2*)(Cf + (size_t)r0*ldout + oc) = make_float2(v[0],v[1]);
                *(float2*)(Cf + (size_t)r1*ldout + oc) = make_float2(v[2],v[3]);
            } else {
                *(__nv_bfloat162*)((__nv_bfloat16*)C + (size_t)r0*ldc + col) = __floats2bfloat162_rn(v[0],v[1]);
                *(__nv_bfloat162*)((__nv_bfloat16*)C + (size_t)r1*ldc + col) = __floats2bfloat162_rn(v[2],v[3]);
            }
        }
    }
}

// ---------------- rmsnorm ----------------
template<typename OutT>
__global__ void rmsnorm_kernel(const float* __restrict__ x,
                               const float* __restrict__ addsrc,
                               const float* __restrict__ w,
                               OutT* __restrict__ out)
{
    int row = blockIdx.x;
    int t = threadIdx.x;
    const float4* x4 = (const float4*)(x + (size_t)row*DMODEL);
    float4 v = x4[t];
    if (addsrc){
        const float4* a4 = (const float4*)(addsrc + (size_t)row*DMODEL);
        float4 a = a4[t];
        v.x+=a.x; v.y+=a.y; v.z+=a.z; v.w+=a.w;
    }
    float ss = v.x*v.x + v.y*v.y + v.z*v.z + v.w*v.w;
    #pragma unroll
    for (int o=16;o;o>>=1) ss += __shfl_xor_sync(0xffffffffu, ss, o);
    __shared__ float sacc[4];
    if ((t&31)==0) sacc[t>>5] = ss;
    __syncthreads();
    float tot = sacc[0]+sacc[1]+sacc[2]+sacc[3];
    float rinv = rsqrtf(tot*(1.0f/(float)DMODEL) + EPSV);
    const float4* w4 = (const float4*)w;
    float4 wv = w4[t];
    float o0=v.x*rinv*wv.x, o1=v.y*rinv*wv.y, o2=v.z*rinv*wv.z, o3=v.w*rinv*wv.w;
    OutT* op = out + (size_t)row*DMODEL + t*4;
    op[0]=(OutT)o0; op[1]=(OutT)o1; op[2]=(OutT)o2; op[3]=(OutT)o3;
}

// ---------------- single-kernel weight conversion (vectorized) ----------------
#define NV_WIN  (2*DINNER*DMODEL/4)     // 262144
#define NV_WXP  (128*DINNER/4)          // 32768
#define NV_WOUT (DMODEL*DINNER/4)       // 131072
#define NV_FUSE (4*DMODEL*DMODEL/4)     // 262144
#define NV_TOT  (NV_WIN+NV_WXP+NV_WOUT+3*NV_FUSE)

__device__ __forceinline__ void cvt4(const float* s, __nv_bfloat16* d, int i){
    float4 v = ((const float4*)s)[i];
    ((__nv_bfloat162*)d)[2*i  ] = __floats2bfloat162_rn(v.x, v.y);
    ((__nv_bfloat162*)d)[2*i+1] = __floats2bfloat162_rn(v.z, v.w);
}
__global__ void convert_all(const float* __restrict__ W_in,
                            const float* __restrict__ W_xproj,
                            const float* __restrict__ W_out,
                            const float* __restrict__ fuse_W,
                            const float* __restrict__ ff_W1,
                            const float* __restrict__ ff_W2)
{
    int i = blockIdx.x*256 + threadIdx.x;
    if (i >= NV_TOT) return;
    if (i < NV_WIN){ cvt4(W_in, g_Win_b, i); return; }
    i -= NV_WIN;
    if (i < NV_WXP){ cvt4(W_xproj + DTRANK*DINNER, g_Wcat_b + DINNER*DINNER, i); return; }
    i -= NV_WXP;
    if (i < NV_WOUT){ cvt4(W_out, g_Wout_b, i); return; }
    i -= NV_WOUT;
    if (i < NV_FUSE){ cvt4(fuse_W, g_fuse_b, i); return; }
    i -= NV_FUSE;
    if (i < NV_FUSE){ cvt4(ff_W1, g_ff1w_b, i); return; }
    i -= NV_FUSE;
    cvt4(ff_W2, g_ff2w_b, i);
}

// W_comb = W_dt[1024,32] @ W_xproj[:32, 1024] -> rows 0..1023 of W_cat
__global__ void wcomb_kernel(const float* __restrict__ W_dt, const float* __restrict__ W_xproj)
{
    int idx = blockIdx.x*256 + threadIdx.x;   // over 1024*1024
    int i = idx >> 10, j = idx & 1023;
    float s = 0.f;
    #pragma unroll
    for (int r=0;r<32;r++) s = fmaf(W_dt[i*32+r], W_xproj[r*DINNER + j], s);
    g_Wcat_b[idx] = __float2bfloat16(s);
}

// ---------------- depthwise causal conv (both directions) + bias + silu -> bf16 ----------------
__global__ void conv_kernel(const float* __restrict__ cw, const float* __restrict__ cb)
{
    int idx = blockIdx.x*256 + threadIdx.x;
    if (idx >= ROWS*DINNER) return;
    int d = idx & (DINNER-1);
    int r = idx >> 10;
    int l = r & (LSEQ-1);
    int b = r >> 10;
    float w0=cw[d*4+0], w1=cw[d*4+1], w2=cw[d*4+2], w3=cw[d*4+3];
    float bias = cb[d];
    const float* up = g_xz + (size_t)(b<<10)*(2*DINNER) + d;
    auto U = [&](int li)->float{ return (li>=0 && li<LSEQ) ? up[(size_t)li*(2*DINNER)] : 0.0f; };
    float um3=U(l-3), um2=U(l-2), um1=U(l-1), u0=U(l), up1=U(l+1), up2=U(l+2), up3=U(l+3);
    float f  = bias + w0*um3 + w1*um2 + w2*um1 + w3*u0;
    float bw = bias + w3*u0  + w2*up1 + w1*up2 + w0*up3;
    g_u_b[0][idx] = __float2bfloat16(siluf_(f));
    g_u_b[1][idx] = __float2bfloat16(siluf_(bw));
}

// ---------------- selective scan v2: block = 16 warps sharing (dir,b); B|C staged in smem ----------------
// grid: (64 dgroups, BATCH, 2 dirs), block 512 threads. Chunks of 64 timesteps, double-buffered.
#define SCAN_T 64
#define SCAN_SMEM (2*SCAN_T*128*4)   // 65536 bytes

__global__ void __launch_bounds__(512)
scan_kernel(const float* __restrict__ A_log, const float* __restrict__ Dskip)
{
    extern __shared__ float sBC[];                 // [2][64][128]
    int tid  = threadIdx.x;
    int warp = tid >> 5, lane = tid & 31;
    int dir  = blockIdx.z;
    int b    = blockIdx.y;
    int d    = blockIdx.x*16 + warp;
    int n0   = lane*2;

    float a0 = -expf(A_log[d*DSTATE + n0]);
    float a1 = -expf(A_log[d*DSTATE + n0 + 1]);
    float dsk = Dskip[d];
    float s0 = 0.f, s1 = 0.f;

    const float* xd = g_xdbl[dir];
    uint32_t sbase = smem_u32_(sBC);

    auto stage = [&](int cc, int buf){
        int row0 = (b<<10) + (dir ? (960 - cc*SCAN_T) : cc*SCAN_T);
        const float* src = xd + (size_t)row0*128;
        uint32_t dstb = sbase + (uint32_t)buf*(SCAN_T*128*4);
        #pragma unroll
        for (int i=0;i<4;i++){
            int idx = i*512 + tid;                 // float4 index, 0..2047
            asm volatile("cp.async.cg.shared.global [%0],[%1],16;"
                         :: "r"(dstb + idx*16), "l"((const void*)(src + idx*4)));
        }
        asm volatile("cp.async.commit_group;");
    };

    stage(0,0);

    intptr_t sD  = dir ? -(intptr_t)DINNER : (intptr_t)DINNER;
    intptr_t s2D = 2*sD;

    for (int cc=0; cc<LSEQ/SCAN_T; cc++){
        asm volatile("cp.async.wait_group 0;" ::: "memory");
        __syncthreads();
        if (cc+1 < LSEQ/SCAN_T) stage(cc+1, (cc+1)&1);

        const float* bcb = sBC + (cc&1)*(SCAN_T*128);
        // global row at local step 0 of this chunk
        size_t gr = (size_t)(b<<10) + (dir ? (1023 - cc*SCAN_T) : cc*SCAN_T);
        const float* dtP = g_dt[dir] + gr*DINNER + d;
        const __nv_bfloat16* uP = g_u_b[dir] + gr*DINNER + d;
        const float* zP  = g_xz + gr*(2*DINNER) + DINNER + d;
        __nv_bfloat16* gP = g_gate_b[dir] + gr*DINNER + d;

        #pragma unroll 1
        for (int jj=0; jj<SCAN_T; jj+=4){
            float p[4], uu[4], zz[4];
            #pragma unroll
            for (int k=0;k<4;k++){
                int lt = jj + k;
                int j  = dir ? (SCAN_T-1-lt) : lt;
                float2 Bv = *(const float2*)(bcb + j*128 + n0);
                float2 Cv = *(const float2*)(bcb + j*128 + 64 + n0);
                float dtv = *dtP;
                uu[k] = __bfloat162float(*uP);
                zz[k] = *zP;
                float dA0 = __expf(dtv*a0);
                float dA1 = __expf(dtv*a1);
                float dtu = dtv*uu[k];
                s0 = fmaf(s0, dA0, dtu*Bv.x);
                s1 = fmaf(s1, dA1, dtu*Bv.y);
                p[k] = s0*Cv.x + s1*Cv.y;
                dtP += sD; uP += sD; zP += s2D;
            }
            // interleaved butterfly reductions (4 independent chains)
            #pragma unroll
            for (int o=16;o;o>>=1){
                p[0] += __shfl_xor_sync(0xffffffffu, p[0], o);
                p[1] += __shfl_xor_sync(0xffffffffu, p[1], o);
                p[2] += __shfl_xor_sync(0xffffffffu, p[2], o);
                p[3] += __shfl_xor_sync(0xffffffffu, p[3], o);
            }
            if (lane==0){
                #pragma unroll
                for (int k=0;k<4;k++){
                    float y = p[k] + uu[k]*dsk;
                    float z = zz[k];
                    gP[(intptr_t)k*sD] = __float2bfloat16(y * (z/(1.0f+__expf(-z))));
                }
            }
            gP += 4*sD;
        }
        __syncthreads();
    }
}

// ---------------- GLU gate + silu -> bf16 ----------------
__global__ void glu_kernel()
{
    int idx = blockIdx.x*256 + threadIdx.x;
    if (idx >= ROWS*DMODEL) return;
    int r = idx >> 9;
    int d = idx & (DMODEL-1);
    float ug = g_uv[(size_t)r*(2*DMODEL) + d];
    float vg = g_uv[(size_t)r*(2*DMODEL) + DMODEL + d];
    float h  = ug * sigmoidf_(vg);
    g_h2_b[idx] = __float2bfloat16(siluf_(h));
}

// ---------------- host side ----------------
template<typename T>
static T* sym_addr(const void* sym)
{
    void* p = nullptr;
    cudaGetSymbolAddress(&p, sym);
    return (T*)p;
}

extern "C" void kernel_launch(void* const* d_in, const int* in_sizes, int n_in,
                              void* d_out, int out_size)
{
    const float* x       = (const float*)d_in[0];
    const float* W_in    = (const float*)d_in[1];
    const float* conv_w  = (const float*)d_in[2];
    const float* conv_b  = (const float*)d_in[3];
    const float* W_xproj = (const float*)d_in[4];
    const float* W_dt    = (const float*)d_in[5];
    const float* b_dt    = (const float*)d_in[6];
    const float* A_log   = (const float*)d_in[7];
    const float* Dskip   = (const float*)d_in[8];
    const float* W_out   = (const float*)d_in[9];
    const float* nin_w   = (const float*)d_in[10];
    const float* fuse_W  = (const float*)d_in[11];
    const float* fuse_b  = (const float*)d_in[12];
    const float* ff_W1   = (const float*)d_in[13];
    const float* ff_W2   = (const float*)d_in[14];
    const float* nout_w  = (const float*)d_in[15];
    float* out = (float*)d_out;

    __nv_bfloat16* p_h    = sym_addr<__nv_bfloat16>(g_h_b);
    float*         p_xz   = sym_addr<float>(g_xz);
    __nv_bfloat16* p_u    = sym_addr<__nv_bfloat16>(g_u_b);
    float*         p_xdbl = sym_addr<float>(g_xdbl);
    float*         p_dt   = sym_addr<float>(g_dt);
    __nv_bfloat16* p_gate = sym_addr<__nv_bfloat16>(g_gate_b);
    __nv_bfloat16* p_hcat = sym_addr<__nv_bfloat16>(g_hcat_b);
    float*         p_uv   = sym_addr<float>(g_uv);
    __nv_bfloat16* p_h2   = sym_addr<__nv_bfloat16>(g_h2_b);
    __nv_bfloat16* p_ff1  = sym_addr<__nv_bfloat16>(g_ff1_b);
    float*         p_ff2  = sym_addr<float>(g_ff2);
    __nv_bfloat16* p_Win  = sym_addr<__nv_bfloat16>(g_Win_b);
    __nv_bfloat16* p_Wcat = sym_addr<__nv_bfloat16>(g_Wcat_b);
    __nv_bfloat16* p_Wout = sym_addr<__nv_bfloat16>(g_Wout_b);
    __nv_bfloat16* p_Wfu  = sym_addr<__nv_bfloat16>(g_fuse_b);
    __nv_bfloat16* p_Wf1  = sym_addr<__nv_bfloat16>(g_ff1w_b);
    __nv_bfloat16* p_Wf2  = sym_addr<__nv_bfloat16>(g_ff2w_b);

    cudaFuncSetAttribute(tc_gemm<0,float>,         cudaFuncAttributeMaxDynamicSharedMemorySize, GEMM_SMEM);
    cudaFuncSetAttribute(tc_gemm<4,float>,         cudaFuncAttributeMaxDynamicSharedMemorySize, GEMM_SMEM);
    cudaFuncSetAttribute(tc_gemm<3,float>,         cudaFuncAttributeMaxDynamicSharedMemorySize, GEMM_SMEM);
    cudaFuncSetAttribute(tc_gemm<0,__nv_bfloat16>, cudaFuncAttributeMaxDynamicSharedMemorySize, GEMM_SMEM);
    cudaFuncSetAttribute(tc_gemm<1,__nv_bfloat16>, cudaFuncAttributeMaxDynamicSharedMemorySize, GEMM_SMEM);
    cudaFuncSetAttribute(scan_kernel,              cudaFuncAttributeMaxDynamicSharedMemorySize, SCAN_SMEM);

    dim3 blk(256);

    // 1. weight conversions (one launch) + combined dt weight
    convert_all<<<(NV_TOT+255)/256, blk>>>(W_in, W_xproj, W_out, fuse_W, ff_W1, ff_W2);
    wcomb_kernel<<<(DINNER*DINNER)/256, blk>>>(W_dt, W_xproj);

    // 2. h = rmsnorm(x) -> bf16
    rmsnorm_kernel<__nv_bfloat16><<<ROWS, 128>>>(x, nullptr, nin_w, p_h);

    // 3. xz = h @ W_in^T   (N=2048, K=512) -> fp32
    tc_gemm<0,float><<<dim3(16,16), blk, GEMM_SMEM>>>(p_h, p_Win, nullptr, p_xz, 2*DINNER, DMODEL,
                                                      0, 0, nullptr, 0);

    // 4. conv + silu, both directions -> bf16
    conv_kernel<<<(ROWS*DINNER)/256, blk>>>(conv_w, conv_b);

    // 5. [dt | BC] = u @ Wcat^T  (N=1152, K=1024), both directions via blockIdx.z
    tc_gemm<4,float><<<dim3(9,16,2), blk, GEMM_SMEM>>>(p_u, p_Wcat, b_dt,
                                                       p_dt, DINNER, DINNER,
                                                       (size_t)ROWS*DINNER, (size_t)ROWS*DINNER,
                                                       p_xdbl, (size_t)ROWS*128);

    // 6. selective scan -> gate bf16
    scan_kernel<<<dim3(64, BATCH, 2), 512, SCAN_SMEM>>>(A_log, Dskip);

    // 7. hcat[:, dir*512:] = gate @ W_out^T (N=512, K=1024), both dirs via z
    tc_gemm<0,__nv_bfloat16><<<dim3(4,16,2), blk, GEMM_SMEM>>>(p_gate, p_Wout, nullptr,
                                                               p_hcat, 2*DMODEL, DINNER,
                                                               (size_t)ROWS*DINNER, (size_t)DMODEL,
                                                               nullptr, 0);

    // 8. uv = hcat @ fuse_W^T + fuse_b  (N=1024, K=1024) -> fp32
    tc_gemm<3,float><<<dim3(8,16), blk, GEMM_SMEM>>>(p_hcat, p_Wfu, fuse_b, p_uv, 2*DMODEL, 2*DMODEL,
                                                     0, 0, nullptr, 0);

    // 9. h2 = silu(ug * sigmoid(vg)) -> bf16
    glu_kernel<<<(ROWS*DMODEL)/256, blk>>>();

    // 10. ff1 = silu(h2 @ ff_W1^T)  (N=2048, K=512) -> bf16
    tc_gemm<1,__nv_bfloat16><<<dim3(16,16), blk, GEMM_SMEM>>>(p_h2, p_Wf1, nullptr, p_ff1, 4*DMODEL, DMODEL,
                                                              0, 0, nullptr, 0);

    // 11. ff2 = ff1 @ ff_W2^T  (N=512, K=2048) -> fp32
    tc_gemm<0,float><<<dim3(4,16), blk, GEMM_SMEM>>>(p_ff1, p_Wf2, nullptr, p_ff2, DMODEL, 4*DMODEL,
                                                     0, 0, nullptr, 0);

    // 12. out = rmsnorm(x + ff2)
    rmsnorm_kernel<float><<<ROWS, 128>>>(x, p_ff2, nout_w, out);
}

// round 13
// speedup vs baseline: 1.8108x; 1.2100x over previous
#include <cuda_runtime.h>
#include <cuda_bf16.h>
#include <math.h>
#include <stdint.h>

// ---------------- problem constants ----------------
#define BATCH   2
#define LSEQ    1024
#define DMODEL  512
#define DINNER  1024
#define DSTATE  64
#define DTRANK  32
#define ROWS    (BATCH*LSEQ)          // 2048
#define EPSV    1e-6f

// ---------------- scratch (device globals; no allocations allowed) ----------------
__device__ __align__(16) __nv_bfloat16 g_h_b   [ROWS*DMODEL];      // rmsnorm(x) bf16
__device__ __align__(16) float         g_xz    [ROWS*2*DINNER];    // h @ W_in^T (u | z) fp32
__device__ __align__(16) __nv_bfloat16 g_u_b   [2][ROWS*DINNER];   // conv+silu bf16
__device__ __align__(16) __nv_bfloat16 g_xdbl_b[2][ROWS*128];      // [B|C] bf16 (128 cols)
__device__ __align__(16) float         g_dt    [2][ROWS*DINNER];   // softplus(dt) fp32
__device__ __align__(16) __nv_bfloat16 g_gate_b[2][ROWS*DINNER];   // (y+u*D)*silu(z) bf16
__device__ __align__(16) __nv_bfloat16 g_hcat_b[ROWS*2*DMODEL];    // [hf|hb] bf16
__device__ __align__(16) float         g_uv    [ROWS*2*DMODEL];    // fuse out fp32
__device__ __align__(16) __nv_bfloat16 g_h2_b  [ROWS*DMODEL];      // silu(glu) bf16
__device__ __align__(16) __nv_bfloat16 g_ff1_b [ROWS*4*DMODEL];    // silu(ff1) bf16
__device__ __align__(16) float         g_ff2   [ROWS*DMODEL];      // ff2 fp32
// bf16 weights
__device__ __align__(16) __nv_bfloat16 g_Win_b [2*DINNER*DMODEL];
__device__ __align__(16) __nv_bfloat16 g_Wcat_b[(DINNER+128)*DINNER]; // [Wcomb(1024) | Wxp(128)] rows
__device__ __align__(16) __nv_bfloat16 g_Wout_b[DMODEL*DINNER];
__device__ __align__(16) __nv_bfloat16 g_fuse_b[2*DMODEL*2*DMODEL];
__device__ __align__(16) __nv_bfloat16 g_ff1w_b[4*DMODEL*DMODEL];
__device__ __align__(16) __nv_bfloat16 g_ff2w_b[DMODEL*4*DMODEL];

// ---------------- math helpers ----------------
__device__ __forceinline__ float sigmoidf_(float x){ return 1.0f/(1.0f+expf(-x)); }
__device__ __forceinline__ float siluf_(float x){ return x/(1.0f+expf(-x)); }
__device__ __forceinline__ float softplusf_(float x){ return (x>20.0f)? x : log1pf(expf(x)); }

__device__ __forceinline__ uint32_t smem_u32_(const void* p){
    uint32_t a;
    asm("{ .reg .u64 t; cvta.to.shared.u64 t, %1; cvt.u32.u64 %0, t; }" : "=r"(a) : "l"(p));
    return a;
}

// ---------------- mma.sync bf16 GEMM: C[M,N] = A[M,K](bf16) @ W[N,K](bf16)^T ----------------
// EPI: 0 none, 1 silu, 3 +bias, 4 split(dt: softplus+bias | BC: none -> C2 bf16)
#define KCHUNK  64
#define SROW    72
#define CHUNK_BYTES (128*SROW*2)          // 18432 per matrix per stage
#define NSTAGE  3
#define GEMM_SMEM (NSTAGE*2*CHUNK_BYTES)  // 110592

__device__ __forceinline__ void ldsm_x4(uint32_t& r0, uint32_t& r1, uint32_t& r2, uint32_t& r3, uint32_t a){
    asm volatile("ldmatrix.sync.aligned.m8n8.x4.shared.b16 {%0,%1,%2,%3},[%4];"
                 : "=r"(r0),"=r"(r1),"=r"(r2),"=r"(r3) : "r"(a));
}
__device__ __forceinline__ void ldsm_x2(uint32_t& r0, uint32_t& r1, uint32_t a){
    asm volatile("ldmatrix.sync.aligned.m8n8.x2.shared.b16 {%0,%1},[%2];"
                 : "=r"(r0),"=r"(r1) : "r"(a));
}
__device__ __forceinline__ void mma16816(float* d, const uint32_t* a, const uint32_t* b){
    asm volatile("mma.sync.aligned.m16n8k16.row.col.f32.bf16.bf16.f32 "
                 "{%0,%1,%2,%3},{%4,%5,%6,%7},{%8,%9},{%0,%1,%2,%3};"
                 : "+f"(d[0]),"+f"(d[1]),"+f"(d[2]),"+f"(d[3])
                 : "r"(a[0]),"r"(a[1]),"r"(a[2]),"r"(a[3]), "r"(b[0]),"r"(b[1]));
}

template<int EPI, typename OutT>
__global__ void __launch_bounds__(256, 2)
tc_gemm(const __nv_bfloat16* __restrict__ A,
        const __nv_bfloat16* __restrict__ W,
        const float* __restrict__ bias,
        OutT* __restrict__ C, int ldc, int K,
        size_t zsA, size_t zsC,
        __nv_bfloat16* __restrict__ C2, size_t zsC2)
{
    extern __shared__ char smem[];
    uint32_t sb = smem_u32_(smem);
    int tid = threadIdx.x, lane = tid & 31, w = tid >> 5;
    int wm = w >> 2, wn = w & 3;              // 2 x 4 warp grid
    int m0 = blockIdx.y*128, n0 = blockIdx.x*128;

    A += (size_t)blockIdx.z * zsA;
    C += (size_t)blockIdx.z * zsC;
    if (EPI==4) C2 += (size_t)blockIdx.z * zsC2;

    const __nv_bfloat16* Abase = A + (size_t)m0*K;
    const __nv_bfloat16* Wbase = W + (size_t)n0*K;
    const int NC = K / KCHUNK;

    auto load_chunk = [&](int c, int s){
        uint32_t abuf = sb + (uint32_t)s*2*CHUNK_BYTES;
        uint32_t bbuf = abuf + CHUNK_BYTES;
        const __nv_bfloat16* Ag = Abase + c*KCHUNK;
        const __nv_bfloat16* Wg = Wbase + c*KCHUNK;
        #pragma unroll
        for (int i=0;i<4;i++){
            int idx = i*256 + tid;            // 0..1023
            int r = idx>>3, cc = idx&7;
            uint32_t dst = (uint32_t)(r*(SROW*2) + cc*16);
            asm volatile("cp.async.cg.shared.global [%0],[%1],16;"
                         :: "r"(abuf+dst), "l"((const void*)(Ag + (size_t)r*K + cc*8)));
            asm volatile("cp.async.cg.shared.global [%0],[%1],16;"
                         :: "r"(bbuf+dst), "l"((const void*)(Wg + (size_t)r*K + cc*8)));
        }
        asm volatile("cp.async.commit_group;");
    };

    float acc[4][4][4];
    #pragma unroll
    for (int i=0;i<4;i++)
        #pragma unroll
        for (int j=0;j<4;j++)
            #pragma unroll
            for (int q=0;q<4;q++) acc[i][j][q]=0.f;

    int a_row  = wm*64 + (lane & 15);
    int a_koff = (lane >> 4) * 8;
    int b_row  = wn*32 + (lane & 7);
    int b_koff = ((lane >> 3) & 1) * 8;

    load_chunk(0,0);
    if (NC>1) load_chunk(1,1);

    for (int c=0;c<NC;c++){
        int s = c % NSTAGE;
        if (c+1<NC) asm volatile("cp.async.wait_group 1;" ::: "memory");
        else        asm volatile("cp.async.wait_group 0;" ::: "memory");
        __syncthreads();
        if (c+2<NC) load_chunk(c+2, (c+2)%NSTAGE);
        uint32_t abuf = sb + (uint32_t)s*2*CHUNK_BYTES;
        uint32_t bbuf = abuf + CHUNK_BYTES;
        #pragma unroll
        for (int ks=0; ks<KCHUNK/16; ks++){
            uint32_t afr[4][4], bfr[4][2];
            #pragma unroll
            for (int mt=0;mt<4;mt++){
                uint32_t addr = abuf + (uint32_t)(((a_row + mt*16)*SROW + ks*16 + a_koff)*2);
                ldsm_x4(afr[mt][0],afr[mt][1],afr[mt][2],afr[mt][3], addr);
            }
            #pragma unroll
            for (int nt=0;nt<4;nt++){
                uint32_t addr = bbuf + (uint32_t)(((b_row + nt*8)*SROW + ks*16 + b_koff)*2);
                ldsm_x2(bfr[nt][0],bfr[nt][1], addr);
            }
            #pragma unroll
            for (int mt=0;mt<4;mt++)
                #pragma unroll
                for (int nt=0;nt<4;nt++)
                    mma16816(acc[mt][nt], afr[mt], bfr[nt]);
        }
    }

    // epilogue
    bool bc_side = (EPI==4) && (n0 >= DINNER);  // BC columns -> C2 (bf16)

    int rbase = m0 + wm*64 + (lane>>2);
    int cbase = n0 + wn*32 + (lane&3)*2;
    #pragma unroll
    for (int mt=0;mt<4;mt++){
        #pragma unroll
        for (int nt=0;nt<4;nt++){
            int col = cbase + nt*8;
            float v[4];
            #pragma unroll
            for (int q=0;q<4;q++){
                float x = acc[mt][nt][q];
                int cc = col + (q&1);
                if (EPI==1) x = siluf_(x);
                else if (EPI==3) x = x + bias[cc];
                else if (EPI==4){ if (!bc_side) x = softplusf_(x + bias[cc]); }
                v[q] = x;
            }
            int r0 = rbase + mt*16, r1 = r0 + 8;
            if (bc_side){
                int oc = col - DINNER;
                *(__nv_bfloat162*)(C2 + (size_t)r0*128 + oc) = __floats2bfloat162_rn(v[0],v[1]);
                *(__nv_bfloat162*)(C2 + (size_t)r1*128 + oc) = __floats2bfloat162_rn(v[2],v[3]);
            } else if (sizeof(OutT)==4){
                *(float2*)((float*)C + (size_t)r0*ldc + col) = make_float2(v[0],v[1]);
                *(float2*)((float*)C + (size_t)r1*ldc + col) = make_float2(v[2],v[3]);
            } else {
                *(__nv_bfloat162*)((__nv_bfloat16*)C + (size_t)r0*ldc + col) = __floats2bfloat162_rn(v[0],v[1]);
                *(__nv_bfloat162*)((__nv_bfloat16*)C + (size_t)r1*ldc + col) = __floats2bfloat162_rn(v[2],v[3]);
            }
        }
    }
}

// ---------------- rmsnorm ----------------
template<typename OutT>
__global__ void rmsnorm_kernel(const float* __restrict__ x,
                               const float* __restrict__ addsrc,
                               const float* __restrict__ w,
                               OutT* __restrict__ out)
{
    int row = blockIdx.x;
    int t = threadIdx.x;
    const float4* x4 = (const float4*)(x + (size_t)row*DMODEL);
    float4 v = x4[t];
    if (addsrc){
        const float4* a4 = (const float4*)(addsrc + (size_t)row*DMODEL);
        float4 a = a4[t];
        v.x+=a.x; v.y+=a.y; v.z+=a.z; v.w+=a.w;
    }
    float ss = v.x*v.x + v.y*v.y + v.z*v.z + v.w*v.w;
    #pragma unroll
    for (int o=16;o;o>>=1) ss += __shfl_xor_sync(0xffffffffu, ss, o);
    __shared__ float sacc[4];
    if ((t&31)==0) sacc[t>>5] = ss;
    __syncthreads();
    float tot = sacc[0]+sacc[1]+sacc[2]+sacc[3];
    float rinv = rsqrtf(tot*(1.0f/(float)DMODEL) + EPSV);
    const float4* w4 = (const float4*)w;
    float4 wv = w4[t];
    float o0=v.x*rinv*wv.x, o1=v.y*rinv*wv.y, o2=v.z*rinv*wv.z, o3=v.w*rinv*wv.w;
    OutT* op = out + (size_t)row*DMODEL + t*4;
    op[0]=(OutT)o0; op[1]=(OutT)o1; op[2]=(OutT)o2; op[3]=(OutT)o3;
}

// ---------------- single-kernel weight conversion + wcomb (merged) ----------------
#define NV_WIN  (2*DINNER*DMODEL/4)     // 262144
#define NV_WXP  (128*DINNER/4)          // 32768
#define NV_WOUT (DMODEL*DINNER/4)       // 131072
#define NV_FUSE (4*DMODEL*DMODEL/4)     // 262144
#define NV_CVT  (NV_WIN+NV_WXP+NV_WOUT+3*NV_FUSE)
#define NV_WCB  (DINNER*DINNER/4)       // 262144 (vectorized wcomb)
#define NV_TOT  (NV_CVT+NV_WCB)

__device__ __forceinline__ void cvt4(const float* s, __nv_bfloat16* d, int i){
    float4 v = ((const float4*)s)[i];
    ((__nv_bfloat162*)d)[2*i  ] = __floats2bfloat162_rn(v.x, v.y);
    ((__nv_bfloat162*)d)[2*i+1] = __floats2bfloat162_rn(v.z, v.w);
}
__global__ void convert_all(const float* __restrict__ W_in,
                            const float* __restrict__ W_xproj,
                            const float* __restrict__ W_out,
                            const float* __restrict__ fuse_W,
                            const float* __restrict__ ff_W1,
                            const float* __restrict__ ff_W2,
                            const float* __restrict__ W_dt)
{
    int i = blockIdx.x*256 + threadIdx.x;
    if (i >= NV_TOT) return;
    if (i < NV_WIN){ cvt4(W_in, g_Win_b, i); return; }
    i -= NV_WIN;
    if (i < NV_WXP){ cvt4(W_xproj + DTRANK*DINNER, g_Wcat_b + DINNER*DINNER, i); return; }
    i -= NV_WXP;
    if (i < NV_WOUT){ cvt4(W_out, g_Wout_b, i); return; }
    i -= NV_WOUT;
    if (i < NV_FUSE){ cvt4(fuse_W, g_fuse_b, i); return; }
    i -= NV_FUSE;
    if (i < NV_FUSE){ cvt4(ff_W1, g_ff1w_b, i); return; }
    i -= NV_FUSE;
    if (i < NV_FUSE){ cvt4(ff_W2, g_ff2w_b, i); return; }
    i -= NV_FUSE;
    // wcomb: W_comb[i4] = W_dt[r_i,:32] @ W_xproj[:32, j4..j4+3]
    {
        int ri = i >> 8;                 // output row 0..1023
        int j4 = (i & 255) * 4;          // output col group
        float4 s = make_float4(0.f,0.f,0.f,0.f);
        #pragma unroll
        for (int r=0;r<32;r++){
            float wd = W_dt[ri*32 + r];
            float4 wx = *(const float4*)&W_xproj[r*DINNER + j4];
            s.x = fmaf(wd, wx.x, s.x); s.y = fmaf(wd, wx.y, s.y);
            s.z = fmaf(wd, wx.z, s.z); s.w = fmaf(wd, wx.w, s.w);
        }
        __nv_bfloat162* dst = (__nv_bfloat162*)&g_Wcat_b[ri*DINNER + j4];
        dst[0] = __floats2bfloat162_rn(s.x, s.y);
        dst[1] = __floats2bfloat162_rn(s.z, s.w);
    }
}

// ---------------- depthwise causal conv (both directions) + bias + silu -> bf16 ----------------
__global__ void conv_kernel(const float* __restrict__ cw, const float* __restrict__ cb)
{
    int idx = blockIdx.x*256 + threadIdx.x;
    if (idx >= ROWS*DINNER) return;
    int d = idx & (DINNER-1);
    int r = idx >> 10;
    int l = r & (LSEQ-1);
    int b = r >> 10;
    float w0=cw[d*4+0], w1=cw[d*4+1], w2=cw[d*4+2], w3=cw[d*4+3];
    float bias = cb[d];
    const float* up = g_xz + (size_t)(b<<10)*(2*DINNER) + d;
    auto U = [&](int li)->float{ return (li>=0 && li<LSEQ) ? up[(size_t)li*(2*DINNER)] : 0.0f; };
    float um3=U(l-3), um2=U(l-2), um1=U(l-1), u0=U(l), up1=U(l+1), up2=U(l+2), up3=U(l+3);
    float f  = bias + w0*um3 + w1*um2 + w2*um1 + w3*u0;
    float bw = bias + w3*u0  + w2*up1 + w1*up2 + w0*up3;
    g_u_b[0][idx] = __float2bfloat16(siluf_(f));
    g_u_b[1][idx] = __float2bfloat16(siluf_(bw));
}

// ---------------- selective scan v3: 16 warps share (dir,b); bf16 B|C in smem; 8-step groups ----------------
#define SCAN_T 64
#define SCAN_SMEM (2*SCAN_T*128*2)   // 32768 bytes (bf16)

__global__ void __launch_bounds__(512)
scan_kernel(const float* __restrict__ A_log, const float* __restrict__ Dskip)
{
    extern __shared__ __nv_bfloat16 sBC[];         // [2][64][128] bf16
    int tid  = threadIdx.x;
    int warp = tid >> 5, lane = tid & 31;
    int dir  = blockIdx.z;
    int b    = blockIdx.y;
    int d    = blockIdx.x*16 + warp;
    int n0   = lane*2;

    float a0 = -expf(A_log[d*DSTATE + n0]);
    float a1 = -expf(A_log[d*DSTATE + n0 + 1]);
    float dsk = Dskip[d];
    float s0 = 0.f, s1 = 0.f;

    const __nv_bfloat16* xd = g_xdbl_b[dir];
    uint32_t sbase = smem_u32_(sBC);

    auto stage = [&](int cc, int buf){
        int row0 = (b<<10) + (dir ? (960 - cc*SCAN_T) : cc*SCAN_T);
        const __nv_bfloat16* src = xd + (size_t)row0*128;
        uint32_t dstb = sbase + (uint32_t)buf*(SCAN_T*128*2);
        #pragma unroll
        for (int i=0;i<2;i++){
            int idx = i*512 + tid;                 // 16B block index, 0..1023
            asm volatile("cp.async.cg.shared.global [%0],[%1],16;"
                         :: "r"(dstb + idx*16), "l"((const void*)(src + idx*8)));
        }
        asm volatile("cp.async.commit_group;");
    };

    stage(0,0);

    intptr_t sD  = dir ? -(intptr_t)DINNER : (intptr_t)DINNER;
    intptr_t s2D = 2*sD;

    for (int cc=0; cc<LSEQ/SCAN_T; cc++){
        asm volatile("cp.async.wait_group 0;" ::: "memory");
        __syncthreads();
        if (cc+1 < LSEQ/SCAN_T) stage(cc+1, (cc+1)&1);

        const __nv_bfloat16* bcb = sBC + (cc&1)*(SCAN_T*128);
        size_t gr = (size_t)(b<<10) + (dir ? (1023 - cc*SCAN_T) : cc*SCAN_T);
        const float* dtP = g_dt[dir] + gr*DINNER + d;
        const __nv_bfloat16* uP = g_u_b[dir] + gr*DINNER + d;
        const float* zP  = g_xz + gr*(2*DINNER) + DINNER + d;
        __nv_bfloat16* gP = g_gate_b[dir] + gr*DINNER + d;

        #pragma unroll 1
        for (int jj=0; jj<SCAN_T; jj+=8){
            float p[8], uu[8], zz[8];
            #pragma unroll
            for (int k=0;k<8;k++){
                int lt = jj + k;
                int j  = dir ? (SCAN_T-1-lt) : lt;
                __nv_bfloat162 bv = *(const __nv_bfloat162*)(bcb + j*128 + n0);
                __nv_bfloat162 cv = *(const __nv_bfloat162*)(bcb + j*128 + 64 + n0);
                float2 Bv = __bfloat1622float2(bv);
                float2 Cv = __bfloat1622float2(cv);
                float dtv = *dtP;
                uu[k] = __bfloat162float(*uP);
                zz[k] = *zP;
                float dA0 = __expf(dtv*a0);
                float dA1 = __expf(dtv*a1);
                float dtu = dtv*uu[k];
                s0 = fmaf(s0, dA0, dtu*Bv.x);
                s1 = fmaf(s1, dA1, dtu*Bv.y);
                p[k] = s0*Cv.x + s1*Cv.y;
                dtP += sD; uP += sD; zP += s2D;
            }
            // interleaved butterfly reductions (8 independent chains)
            #pragma unroll
            for (int o=16;o;o>>=1){
                #pragma unroll
                for (int k=0;k<8;k++) p[k] += __shfl_xor_sync(0xffffffffu, p[k], o);
            }
            // gate epilogue spread over lanes 0..7 (select via ternary tree)
            {
                float t01,t23,t45,t67,tA,tB,pv,uv,zv;
                t01=(lane&1)?p[1]:p[0]; t23=(lane&1)?p[3]:p[2];
                t45=(lane&1)?p[5]:p[4]; t67=(lane&1)?p[7]:p[6];
                tA=(lane&2)?t23:t01; tB=(lane&2)?t67:t45; pv=(lane&4)?tB:tA;
                t01=(lane&1)?uu[1]:uu[0]; t23=(lane&1)?uu[3]:uu[2];
                t45=(lane&1)?uu[5]:uu[4]; t67=(lane&1)?uu[7]:uu[6];
                tA=(lane&2)?t23:t01; tB=(lane&2)?t67:t45; uv=(lane&4)?tB:tA;
                t01=(lane&1)?zz[1]:zz[0]; t23=(lane&1)?zz[3]:zz[2];
                t45=(lane&1)?zz[5]:zz[4]; t67=(lane&1)?zz[7]:zz[6];
                tA=(lane&2)?t23:t01; tB=(lane&2)?t67:t45; zv=(lane&4)?tB:tA;
                if (lane < 8){
                    float y = pv + uv*dsk;
                    gP[(intptr_t)lane*sD] = __float2bfloat16(y * (zv/(1.0f+__expf(-zv))));
                }
            }
            gP += 8*sD;
        }
        __syncthreads();
    }
}

// ---------------- GLU gate + silu -> bf16 ----------------
__global__ void glu_kernel()
{
    int idx = blockIdx.x*256 + threadIdx.x;
    if (idx >= ROWS*DMODEL) return;
    int r = idx >> 9;
    int d = idx & (DMODEL-1);
    float ug = g_uv[(size_t)r*(2*DMODEL) + d];
    float vg = g_uv[(size_t)r*(2*DMODEL) + DMODEL + d];
    float h  = ug * sigmoidf_(vg);
    g_h2_b[idx] = __float2bfloat16(siluf_(h));
}

// ---------------- host side ----------------
template<typename T>
static T* sym_addr(const void* sym)
{
    void* p = nullptr;
    cudaGetSymbolAddress(&p, sym);
    return (T*)p;
}

extern "C" void kernel_launch(void* const* d_in, const int* in_sizes, int n_in,
                              void* d_out, int out_size)
{
    const float* x       = (const float*)d_in[0];
    const float* W_in    = (const float*)d_in[1];
    const float* conv_w  = (const float*)d_in[2];
    const float* conv_b  = (const float*)d_in[3];
    const float* W_xproj = (const float*)d_in[4];
    const float* W_dt    = (const float*)d_in[5];
    const float* b_dt    = (const float*)d_in[6];
    const float* A_log   = (const float*)d_in[7];
    const float* Dskip   = (const float*)d_in[8];
    const float* W_out   = (const float*)d_in[9];
    const float* nin_w   = (const float*)d_in[10];
    const float* fuse_W  = (const float*)d_in[11];
    const float* fuse_b  = (const float*)d_in[12];
    const float* ff_W1   = (const float*)d_in[13];
    const float* ff_W2   = (const float*)d_in[14];
    const float* nout_w  = (const float*)d_in[15];
    float* out = (float*)d_out;

    __nv_bfloat16* p_h    = sym_addr<__nv_bfloat16>(g_h_b);
    float*         p_xz   = sym_addr<float>(g_xz);
    __nv_bfloat16* p_u    = sym_addr<__nv_bfloat16>(g_u_b);
    __nv_bfloat16* p_xdbl = sym_addr<__nv_bfloat16>(g_xdbl_b);
    float*         p_dt   = sym_addr<float>(g_dt);
    __nv_bfloat16* p_gate = sym_addr<__nv_bfloat16>(g_gate_b);
    __nv_bfloat16* p_hcat = sym_addr<__nv_bfloat16>(g_hcat_b);
    float*         p_uv   = sym_addr<float>(g_uv);
    __nv_bfloat16* p_h2   = sym_addr<__nv_bfloat16>(g_h2_b);
    __nv_bfloat16* p_ff1  = sym_addr<__nv_bfloat16>(g_ff1_b);
    float*         p_ff2  = sym_addr<float>(g_ff2);
    __nv_bfloat16* p_Win  = sym_addr<__nv_bfloat16>(g_Win_b);
    __nv_bfloat16* p_Wcat = sym_addr<__nv_bfloat16>(g_Wcat_b);
    __nv_bfloat16* p_Wout = sym_addr<__nv_bfloat16>(g_Wout_b);
    __nv_bfloat16* p_Wfu  = sym_addr<__nv_bfloat16>(g_fuse_b);
    __nv_bfloat16* p_Wf1  = sym_addr<__nv_bfloat16>(g_ff1w_b);
    __nv_bfloat16* p_Wf2  = sym_addr<__nv_bfloat16>(g_ff2w_b);

    cudaFuncSetAttribute(tc_gemm<0,float>,         cudaFuncAttributeMaxDynamicSharedMemorySize, GEMM_SMEM);
    cudaFuncSetAttribute(tc_gemm<4,float>,         cudaFuncAttributeMaxDynamicSharedMemorySize, GEMM_SMEM);
    cudaFuncSetAttribute(tc_gemm<3,float>,         cudaFuncAttributeMaxDynamicSharedMemorySize, GEMM_SMEM);
    cudaFuncSetAttribute(tc_gemm<0,__nv_bfloat16>, cudaFuncAttributeMaxDynamicSharedMemorySize, GEMM_SMEM);
    cudaFuncSetAttribute(tc_gemm<1,__nv_bfloat16>, cudaFuncAttributeMaxDynamicSharedMemorySize, GEMM_SMEM);
    cudaFuncSetAttribute(scan_kernel,              cudaFuncAttributeMaxDynamicSharedMemorySize, SCAN_SMEM);

    dim3 blk(256);

    // 1. weight conversions + wcomb (single launch)
    convert_all<<<(NV_TOT+255)/256, blk>>>(W_in, W_xproj, W_out, fuse_W, ff_W1, ff_W2, W_dt);

    // 2. h = rmsnorm(x) -> bf16
    rmsnorm_kernel<__nv_bfloat16><<<ROWS, 128>>>(x, nullptr, nin_w, p_h);

    // 3. xz = h @ W_in^T   (N=2048, K=512) -> fp32
    tc_gemm<0,float><<<dim3(16,16), blk, GEMM_SMEM>>>(p_h, p_Win, nullptr, p_xz, 2*DINNER, DMODEL,
                                                      0, 0, nullptr, 0);

    // 4. conv + silu, both directions -> bf16
    conv_kernel<<<(ROWS*DINNER)/256, blk>>>(conv_w, conv_b);

    // 5. [dt | BC] = u @ Wcat^T  (N=1152, K=1024), both directions via blockIdx.z; BC -> bf16
    tc_gemm<4,float><<<dim3(9,16,2), blk, GEMM_SMEM>>>(p_u, p_Wcat, b_dt,
                                                       p_dt, DINNER, DINNER,
                                                       (size_t)ROWS*DINNER, (size_t)ROWS*DINNER,
                                                       p_xdbl, (size_t)ROWS*128);

    // 6. selective scan -> gate bf16   (launch slot 6: ncu -s 5 should land here)
    scan_kernel<<<dim3(64, BATCH, 2), 512, SCAN_SMEM>>>(A_log, Dskip);

    // 7. hcat[:, dir*512:] = gate @ W_out^T (N=512, K=1024), both dirs via z
    tc_gemm<0,__nv_bfloat16><<<dim3(4,16,2), blk, GEMM_SMEM>>>(p_gate, p_Wout, nullptr,
                                                               p_hcat, 2*DMODEL, DINNER,
                                                               (size_t)ROWS*DINNER, (size_t)DMODEL,
                                                               nullptr, 0);

    // 8. uv = hcat @ fuse_W^T + fuse_b  (N=1024, K=1024) -> fp32
    tc_gemm<3,float><<<dim3(8,16), blk, GEMM_SMEM>>>(p_hcat, p_Wfu, fuse_b, p_uv, 2*DMODEL, 2*DMODEL,
                                                     0, 0, nullptr, 0);

    // 9. h2 = silu(ug * sigmoid(vg)) -> bf16
    glu_kernel<<<(ROWS*DMODEL)/256, blk>>>();

    // 10. ff1 = silu(h2 @ ff_W1^T)  (N=2048, K=512) -> bf16
    tc_gemm<1,__nv_bfloat16><<<dim3(16,16), blk, GEMM_SMEM>>>(p_h2, p_Wf1, nullptr, p_ff1, 4*DMODEL, DMODEL,
                                                              0, 0, nullptr, 0);

    // 11. ff2 = ff1 @ ff_W2^T  (N=512, K=2048) -> fp32
    tc_gemm<0,float><<<dim3(4,16), blk, GEMM_SMEM>>>(p_ff1, p_Wf2, nullptr, p_ff2, DMODEL, 4*DMODEL,
                                                     0, 0, nullptr, 0);

    // 12. out = rmsnorm(x + ff2)
    rmsnorm_kernel<float><<<ROWS, 128>>>(x, p_ff2, nout_w, out);
}

// round 14
// speedup vs baseline: 2.0900x; 1.1542x over previous
#include <cuda_runtime.h>
#include <cuda_bf16.h>
#include <math.h>
#include <stdint.h>

// ---------------- problem constants ----------------
#define BATCH   2
#define LSEQ    1024
#define DMODEL  512
#define DINNER  1024
#define DSTATE  64
#define DTRANK  32
#define ROWS    (BATCH*LSEQ)          // 2048
#define EPSV    1e-6f

// ---------------- scratch (device globals; no allocations allowed) ----------------
__device__ __align__(16) __nv_bfloat16 g_h_b   [ROWS*DMODEL];      // rmsnorm(x) bf16
__device__ __align__(16) float         g_xz    [ROWS*2*DINNER];    // h @ W_in^T (u | z) fp32
__device__ __align__(16) __nv_bfloat16 g_u_b   [2][ROWS*DINNER];   // conv+silu bf16
__device__ __align__(16) __nv_bfloat16 g_xdbl_b[2][ROWS*128];      // [B|C] bf16, pair-interleaved
__device__ __align__(16) float         g_dt    [2][ROWS*DINNER];   // softplus(dt) fp32
__device__ __align__(16) __nv_bfloat16 g_gate_b[2][ROWS*DINNER];   // (y+u*D)*silu(z) bf16
__device__ __align__(16) __nv_bfloat16 g_hcat_b[ROWS*2*DMODEL];    // [hf|hb] bf16
__device__ __align__(16) float         g_uv    [ROWS*2*DMODEL];    // fuse out fp32
__device__ __align__(16) __nv_bfloat16 g_h2_b  [ROWS*DMODEL];      // silu(glu) bf16
__device__ __align__(16) __nv_bfloat16 g_ff1_b [ROWS*4*DMODEL];    // silu(ff1) bf16
__device__ __align__(16) float         g_ff2   [ROWS*DMODEL];      // ff2 fp32
// bf16 weights
__device__ __align__(16) __nv_bfloat16 g_Win_b [2*DINNER*DMODEL];
__device__ __align__(16) __nv_bfloat16 g_Wcat_b[(DINNER+128)*DINNER]; // [Wcomb(1024) | Wxp(128)] rows
__device__ __align__(16) __nv_bfloat16 g_Wout_b[DMODEL*DINNER];
__device__ __align__(16) __nv_bfloat16 g_fuse_b[2*DMODEL*2*DMODEL];
__device__ __align__(16) __nv_bfloat16 g_ff1w_b[4*DMODEL*DMODEL];
__device__ __align__(16) __nv_bfloat16 g_ff2w_b[DMODEL*4*DMODEL];

// ---------------- math helpers ----------------
__device__ __forceinline__ float sigmoidf_(float x){ return 1.0f/(1.0f+expf(-x)); }
__device__ __forceinline__ float siluf_(float x){ return x/(1.0f+expf(-x)); }
__device__ __forceinline__ float softplusf_(float x){ return (x>20.0f)? x : log1pf(expf(x)); }

__device__ __forceinline__ uint32_t smem_u32_(const void* p){
    uint32_t a;
    asm("{ .reg .u64 t; cvta.to.shared.u64 t, %1; cvt.u32.u64 %0, t; }" : "=r"(a) : "l"(p));
    return a;
}

// ---------------- mma.sync bf16 GEMM: C[M,N] = A[M,K](bf16) @ W[N,K](bf16)^T ----------------
// EPI: 0 none, 1 silu, 3 +bias, 4 split(dt: softplus+bias | BC: none -> C2 bf16 interleaved)
#define KCHUNK  64
#define SROW    72
#define CHUNK_BYTES (128*SROW*2)          // 18432 per matrix per stage
#define NSTAGE  3
#define GEMM_SMEM (NSTAGE*2*CHUNK_BYTES)  // 110592

__device__ __forceinline__ void ldsm_x4(uint32_t& r0, uint32_t& r1, uint32_t& r2, uint32_t& r3, uint32_t a){
    asm volatile("ldmatrix.sync.aligned.m8n8.x4.shared.b16 {%0,%1,%2,%3},[%4];"
                 : "=r"(r0),"=r"(r1),"=r"(r2),"=r"(r3) : "r"(a));
}
__device__ __forceinline__ void ldsm_x2(uint32_t& r0, uint32_t& r1, uint32_t a){
    asm volatile("ldmatrix.sync.aligned.m8n8.x2.shared.b16 {%0,%1},[%2];"
                 : "=r"(r0),"=r"(r1) : "r"(a));
}
__device__ __forceinline__ void mma16816(float* d, const uint32_t* a, const uint32_t* b){
    asm volatile("mma.sync.aligned.m16n8k16.row.col.f32.bf16.bf16.f32 "
                 "{%0,%1,%2,%3},{%4,%5,%6,%7},{%8,%9},{%0,%1,%2,%3};"
                 : "+f"(d[0]),"+f"(d[1]),"+f"(d[2]),"+f"(d[3])
                 : "r"(a[0]),"r"(a[1]),"r"(a[2]),"r"(a[3]), "r"(b[0]),"r"(b[1]));
}

template<int EPI, typename OutT>
__global__ void __launch_bounds__(256, 2)
tc_gemm(const __nv_bfloat16* __restrict__ A,
        const __nv_bfloat16* __restrict__ W,
        const float* __restrict__ bias,
        OutT* __restrict__ C, int ldc, int K,
        size_t zsA, size_t zsC,
        __nv_bfloat16* __restrict__ C2, size_t zsC2)
{
    extern __shared__ char smem[];
    uint32_t sb = smem_u32_(smem);
    int tid = threadIdx.x, lane = tid & 31, w = tid >> 5;
    int wm = w >> 2, wn = w & 3;              // 2 x 4 warp grid
    int m0 = blockIdx.y*128, n0 = blockIdx.x*128;

    A += (size_t)blockIdx.z * zsA;
    C += (size_t)blockIdx.z * zsC;
    if (EPI==4) C2 += (size_t)blockIdx.z * zsC2;

    const __nv_bfloat16* Abase = A + (size_t)m0*K;
    const __nv_bfloat16* Wbase = W + (size_t)n0*K;
    const int NC = K / KCHUNK;

    auto load_chunk = [&](int c, int s){
        uint32_t abuf = sb + (uint32_t)s*2*CHUNK_BYTES;
        uint32_t bbuf = abuf + CHUNK_BYTES;
        const __nv_bfloat16* Ag = Abase + c*KCHUNK;
        const __nv_bfloat16* Wg = Wbase + c*KCHUNK;
        #pragma unroll
        for (int i=0;i<4;i++){
            int idx = i*256 + tid;            // 0..1023
            int r = idx>>3, cc = idx&7;
            uint32_t dst = (uint32_t)(r*(SROW*2) + cc*16);
            asm volatile("cp.async.cg.shared.global [%0],[%1],16;"
                         :: "r"(abuf+dst), "l"((const void*)(Ag + (size_t)r*K + cc*8)));
            asm volatile("cp.async.cg.shared.global [%0],[%1],16;"
                         :: "r"(bbuf+dst), "l"((const void*)(Wg + (size_t)r*K + cc*8)));
        }
        asm volatile("cp.async.commit_group;");
    };

    float acc[4][4][4];
    #pragma unroll
    for (int i=0;i<4;i++)
        #pragma unroll
        for (int j=0;j<4;j++)
            #pragma unroll
            for (int q=0;q<4;q++) acc[i][j][q]=0.f;

    int a_row  = wm*64 + (lane & 15);
    int a_koff = (lane >> 4) * 8;
    int b_row  = wn*32 + (lane & 7);
    int b_koff = ((lane >> 3) & 1) * 8;

    load_chunk(0,0);
    if (NC>1) load_chunk(1,1);

    for (int c=0;c<NC;c++){
        int s = c % NSTAGE;
        if (c+1<NC) asm volatile("cp.async.wait_group 1;" ::: "memory");
        else        asm volatile("cp.async.wait_group 0;" ::: "memory");
        __syncthreads();
        if (c+2<NC) load_chunk(c+2, (c+2)%NSTAGE);
        uint32_t abuf = sb + (uint32_t)s*2*CHUNK_BYTES;
        uint32_t bbuf = abuf + CHUNK_BYTES;
        #pragma unroll
        for (int ks=0; ks<KCHUNK/16; ks++){
            uint32_t afr[4][4], bfr[4][2];
            #pragma unroll
            for (int mt=0;mt<4;mt++){
                uint32_t addr = abuf + (uint32_t)(((a_row + mt*16)*SROW + ks*16 + a_koff)*2);
                ldsm_x4(afr[mt][0],afr[mt][1],afr[mt][2],afr[mt][3], addr);
            }
            #pragma unroll
            for (int nt=0;nt<4;nt++){
                uint32_t addr = bbuf + (uint32_t)(((b_row + nt*8)*SROW + ks*16 + b_koff)*2);
                ldsm_x2(bfr[nt][0],bfr[nt][1], addr);
            }
            #pragma unroll
            for (int mt=0;mt<4;mt++)
                #pragma unroll
                for (int nt=0;nt<4;nt++)
                    mma16816(acc[mt][nt], afr[mt], bfr[nt]);
        }
    }

    // epilogue
    bool bc_side = (EPI==4) && (n0 >= DINNER);  // BC columns -> C2 (bf16, pair-interleaved)

    int rbase = m0 + wm*64 + (lane>>2);
    int cbase = n0 + wn*32 + (lane&3)*2;
    #pragma unroll
    for (int mt=0;mt<4;mt++){
        #pragma unroll
        for (int nt=0;nt<4;nt++){
            int col = cbase + nt*8;
            float v[4];
            #pragma unroll
            for (int q=0;q<4;q++){
                float x = acc[mt][nt][q];
                int cc = col + (q&1);
                if (EPI==1) x = siluf_(x);
                else if (EPI==3) x = x + bias[cc];
                else if (EPI==4){ if (!bc_side) x = softplusf_(x + bias[cc]); }
                v[q] = x;
            }
            int r0 = rbase + mt*16, r1 = r0 + 8;
            if (bc_side){
                // interleave: out col layout [B0 B1 C0 C1 B2 B3 C2 C3 ...]
                int oc = col - DINNER;       // even, 0..126
                int pos = (oc < 64) ? ((oc>>1)*4) : (((oc-64)>>1)*4 + 2);
                *(__nv_bfloat162*)(C2 + (size_t)r0*128 + pos) = __floats2bfloat162_rn(v[0],v[1]);
                *(__nv_bfloat162*)(C2 + (size_t)r1*128 + pos) = __floats2bfloat162_rn(v[2],v[3]);
            } else if (sizeof(OutT)==4){
                *(float2*)((float*)C + (size_t)r0*ldc + col) = make_float2(v[0],v[1]);
                *(float2*)((float*)C + (size_t)r1*ldc + col) = make_float2(v[2],v[3]);
            } else {
                *(__nv_bfloat162*)((__nv_bfloat16*)C + (size_t)r0*ldc + col) = __floats2bfloat162_rn(v[0],v[1]);
                *(__nv_bfloat162*)((__nv_bfloat16*)C + (size_t)r1*ldc + col) = __floats2bfloat162_rn(v[2],v[3]);
            }
        }
    }
}

// ---------------- rmsnorm ----------------
template<typename OutT>
__global__ void rmsnorm_kernel(const float* __restrict__ x,
                               const float* __restrict__ addsrc,
                               const float* __restrict__ w,
                               OutT* __restrict__ out)
{
    int row = blockIdx.x;
    int t = threadIdx.x;
    const float4* x4 = (const float4*)(x + (size_t)row*DMODEL);
    float4 v = x4[t];
    if (addsrc){
        const float4* a4 = (const float4*)(addsrc + (size_t)row*DMODEL);
        float4 a = a4[t];
        v.x+=a.x; v.y+=a.y; v.z+=a.z; v.w+=a.w;
    }
    float ss = v.x*v.x + v.y*v.y + v.z*v.z + v.w*v.w;
    #pragma unroll
    for (int o=16;o;o>>=1) ss += __shfl_xor_sync(0xffffffffu, ss, o);
    __shared__ float sacc[4];
    if ((t&31)==0) sacc[t>>5] = ss;
    __syncthreads();
    float tot = sacc[0]+sacc[1]+sacc[2]+sacc[3];
    float rinv = rsqrtf(tot*(1.0f/(float)DMODEL) + EPSV);
    const float4* w4 = (const float4*)w;
    float4 wv = w4[t];
    float o0=v.x*rinv*wv.x, o1=v.y*rinv*wv.y, o2=v.z*rinv*wv.z, o3=v.w*rinv*wv.w;
    OutT* op = out + (size_t)row*DMODEL + t*4;
    op[0]=(OutT)o0; op[1]=(OutT)o1; op[2]=(OutT)o2; op[3]=(OutT)o3;
}

// ---------------- single-kernel weight conversion + wcomb (merged) ----------------
#define NV_WIN  (2*DINNER*DMODEL/4)     // 262144
#define NV_WXP  (128*DINNER/4)          // 32768
#define NV_WOUT (DMODEL*DINNER/4)       // 131072
#define NV_FUSE (4*DMODEL*DMODEL/4)     // 262144
#define NV_CVT  (NV_WIN+NV_WXP+NV_WOUT+3*NV_FUSE)
#define NV_WCB  (DINNER*DINNER/4)       // 262144 (vectorized wcomb)
#define NV_TOT  (NV_CVT+NV_WCB)

__device__ __forceinline__ void cvt4(const float* s, __nv_bfloat16* d, int i){
    float4 v = ((const float4*)s)[i];
    ((__nv_bfloat162*)d)[2*i  ] = __floats2bfloat162_rn(v.x, v.y);
    ((__nv_bfloat162*)d)[2*i+1] = __floats2bfloat162_rn(v.z, v.w);
}
__global__ void convert_all(const float* __restrict__ W_in,
                            const float* __restrict__ W_xproj,
                            const float* __restrict__ W_out,
                            const float* __restrict__ fuse_W,
                            const float* __restrict__ ff_W1,
                            const float* __restrict__ ff_W2,
                            const float* __restrict__ W_dt)
{
    int i = blockIdx.x*256 + threadIdx.x;
    if (i >= NV_TOT) return;
    if (i < NV_WIN){ cvt4(W_in, g_Win_b, i); return; }
    i -= NV_WIN;
    if (i < NV_WXP){ cvt4(W_xproj + DTRANK*DINNER, g_Wcat_b + DINNER*DINNER, i); return; }
    i -= NV_WXP;
    if (i < NV_WOUT){ cvt4(W_out, g_Wout_b, i); return; }
    i -= NV_WOUT;
    if (i < NV_FUSE){ cvt4(fuse_W, g_fuse_b, i); return; }
    i -= NV_FUSE;
    if (i < NV_FUSE){ cvt4(ff_W1, g_ff1w_b, i); return; }
    i -= NV_FUSE;
    if (i < NV_FUSE){ cvt4(ff_W2, g_ff2w_b, i); return; }
    i -= NV_FUSE;
    // wcomb: W_comb[i4] = W_dt[r_i,:32] @ W_xproj[:32, j4..j4+3]
    {
        int ri = i >> 8;                 // output row 0..1023
        int j4 = (i & 255) * 4;          // output col group
        float4 s = make_float4(0.f,0.f,0.f,0.f);
        #pragma unroll
        for (int r=0;r<32;r++){
            float wd = W_dt[ri*32 + r];
            float4 wx = *(const float4*)&W_xproj[r*DINNER + j4];
            s.x = fmaf(wd, wx.x, s.x); s.y = fmaf(wd, wx.y, s.y);
            s.z = fmaf(wd, wx.z, s.z); s.w = fmaf(wd, wx.w, s.w);
        }
        __nv_bfloat162* dst = (__nv_bfloat162*)&g_Wcat_b[ri*DINNER + j4];
        dst[0] = __floats2bfloat162_rn(s.x, s.y);
        dst[1] = __floats2bfloat162_rn(s.z, s.w);
    }
}

// ---------------- depthwise causal conv (both directions) + bias + silu -> bf16 ----------------
__global__ void conv_kernel(const float* __restrict__ cw, const float* __restrict__ cb)
{
    int idx = blockIdx.x*256 + threadIdx.x;
    if (idx >= ROWS*DINNER) return;
    int d = idx & (DINNER-1);
    int r = idx >> 10;
    int l = r & (LSEQ-1);
    int b = r >> 10;
    float w0=cw[d*4+0], w1=cw[d*4+1], w2=cw[d*4+2], w3=cw[d*4+3];
    float bias = cb[d];
    const float* up = g_xz + (size_t)(b<<10)*(2*DINNER) + d;
    auto U = [&](int li)->float{ return (li>=0 && li<LSEQ) ? up[(size_t)li*(2*DINNER)] : 0.0f; };
    float um3=U(l-3), um2=U(l-2), um1=U(l-1), u0=U(l), up1=U(l+1), up2=U(l+2), up3=U(l+3);
    float f  = bias + w0*um3 + w1*um2 + w2*um1 + w3*u0;
    float bw = bias + w3*u0  + w2*up1 + w1*up2 + w0*up3;
    g_u_b[0][idx] = __float2bfloat16(siluf_(f));
    g_u_b[1][idx] = __float2bfloat16(siluf_(bw));
}

// ---------------- selective scan v4: butterfly reduce-scatter, 1 SHFL/step ----------------
#define SCAN_T 64
#define SCAN_SMEM (2*SCAN_T*128*2)   // 32768 bytes (bf16)

template<int DIR>
__device__ __forceinline__ void scan_body(const float* __restrict__ A_log,
                                          const float* __restrict__ Dskip,
                                          __nv_bfloat16* sBC)
{
    constexpr intptr_t STR  = DIR ? -(intptr_t)DINNER : (intptr_t)DINNER;
    constexpr intptr_t STRZ = 2*STR;
    int tid  = threadIdx.x;
    int warp = tid >> 5, lane = tid & 31;
    int b    = blockIdx.y;
    int d    = blockIdx.x*16 + warp;
    int n0   = lane*2;

    float a0 = -expf(A_log[d*DSTATE + n0]);
    float a1 = -expf(A_log[d*DSTATE + n0 + 1]);
    float dsk = Dskip[d];
    float s0 = 0.f, s1 = 0.f;

    const __nv_bfloat16* xd = g_xdbl_b[DIR];
    uint32_t sbase = smem_u32_(sBC);

    auto stage = [&](int cc, int buf){
        int row0 = (b<<10) + (DIR ? (960 - cc*SCAN_T) : cc*SCAN_T);
        const __nv_bfloat16* src = xd + (size_t)row0*128;
        uint32_t dstb = sbase + (uint32_t)buf*(SCAN_T*128*2);
        #pragma unroll
        for (int i=0;i<2;i++){
            int idx = i*512 + tid;                 // 16B block index
            asm volatile("cp.async.cg.shared.global [%0],[%1],16;"
                         :: "r"(dstb + idx*16), "l"((const void*)(src + idx*8)));
        }
        asm volatile("cp.async.commit_group;");
    };

    stage(0,0);

    for (int cc=0; cc<LSEQ/SCAN_T; cc++){
        asm volatile("cp.async.wait_group 0;" ::: "memory");
        __syncthreads();
        if (cc+1 < LSEQ/SCAN_T) stage(cc+1, (cc+1)&1);

        const __nv_bfloat16* bcb = sBC + (cc&1)*(SCAN_T*128);
        size_t gr = (size_t)(b<<10) + (DIR ? (1023 - cc*SCAN_T) : cc*SCAN_T);
        const float* dtP = g_dt[DIR] + gr*DINNER + d;
        const __nv_bfloat16* uP = g_u_b[DIR] + gr*DINNER + d;
        const float* zP  = g_xz + gr*(2*DINNER) + DINNER + d;
        __nv_bfloat16* gP = g_gate_b[DIR] + gr*DINNER + d;

        #pragma unroll 1
        for (int jj=0; jj<SCAN_T; jj+=16){
            float p[16];
            #pragma unroll
            for (int k=0;k<16;k++){
                int lt = jj + k;
                int j  = DIR ? (SCAN_T-1-lt) : lt;
                uint2 bc = *(const uint2*)(bcb + j*128 + lane*4);   // [B0 B1 C0 C1] for this lane
                float2 Bv = __bfloat1622float2(*(__nv_bfloat162*)&bc.x);
                float2 Cv = __bfloat1622float2(*(__nv_bfloat162*)&bc.y);
                float dtv = __ldg(dtP + (intptr_t)lt*STR);
                float uu  = __bfloat162float(__ldg(uP + (intptr_t)lt*STR));
                float dA0 = __expf(dtv*a0);
                float dA1 = __expf(dtv*a1);
                float dtu = dtv*uu;
                s0 = fmaf(s0, dA0, dtu*Bv.x);
                s1 = fmaf(s1, dA1, dtu*Bv.y);
                p[k] = s0*Cv.x + s1*Cv.y;
            }
            // butterfly reduce-scatter: after 5 levels lane pair (2c,2c+1) holds full sum of chain c
            float q8[8];
            #pragma unroll
            for (int k=0;k<8;k++){
                float got = __shfl_xor_sync(0xffffffffu, (lane&16)? p[k] : p[k+8], 16);
                q8[k] = ((lane&16)? p[k+8] : p[k]) + got;
            }
            float q4[4];
            #pragma unroll
            for (int k=0;k<4;k++){
                float got = __shfl_xor_sync(0xffffffffu, (lane&8)? q8[k] : q8[k+4], 8);
                q4[k] = ((lane&8)? q8[k+4] : q8[k]) + got;
            }
            float q2[2];
            #pragma unroll
            for (int k=0;k<2;k++){
                float got = __shfl_xor_sync(0xffffffffu, (lane&4)? q4[k] : q4[k+2], 4);
                q2[k] = ((lane&4)? q4[k+2] : q4[k]) + got;
            }
            float got1 = __shfl_xor_sync(0xffffffffu, (lane&2)? q2[0] : q2[1], 2);
            float q1 = ((lane&2)? q2[1] : q2[0]) + got1;
            q1 += __shfl_xor_sync(0xffffffffu, q1, 1);

            int c  = lane >> 1;            // chain (timestep within group) owned by this lane pair
            int lt = jj + c;
            if (!(lane & 1)){
                float uu = __bfloat162float(__ldg(uP + (intptr_t)lt*STR));
                float z  = __ldg(zP + (intptr_t)lt*STRZ);
                float y  = q1 + uu*dsk;
                gP[(intptr_t)lt*STR] = __float2bfloat16(y * (z/(1.0f+__expf(-z))));
            }
        }
        __syncthreads();
    }
}

__global__ void __launch_bounds__(512)
scan_kernel(const float* __restrict__ A_log, const float* __restrict__ Dskip)
{
    extern __shared__ __nv_bfloat16 sBC[];
    if (blockIdx.z == 0) scan_body<0>(A_log, Dskip, sBC);
    else                 scan_body<1>(A_log, Dskip, sBC);
}

// ---------------- GLU gate + silu -> bf16 ----------------
__global__ void glu_kernel()
{
    int idx = blockIdx.x*256 + threadIdx.x;
    if (idx >= ROWS*DMODEL) return;
    int r = idx >> 9;
    int d = idx & (DMODEL-1);
    float ug = g_uv[(size_t)r*(2*DMODEL) + d];
    float vg = g_uv[(size_t)r*(2*DMODEL) + DMODEL + d];
    float h  = ug * sigmoidf_(vg);
    g_h2_b[idx] = __float2bfloat16(siluf_(h));
}

// ---------------- host side ----------------
template<typename T>
static T* sym_addr(const void* sym)
{
    void* p = nullptr;
    cudaGetSymbolAddress(&p, sym);
    return (T*)p;
}

extern "C" void kernel_launch(void* const* d_in, const int* in_sizes, int n_in,
                              void* d_out, int out_size)
{
    const float* x       = (const float*)d_in[0];
    const float* W_in    = (const float*)d_in[1];
    const float* conv_w  = (const float*)d_in[2];
    const float* conv_b  = (const float*)d_in[3];
    const float* W_xproj = (const float*)d_in[4];
    const float* W_dt    = (const float*)d_in[5];
    const float* b_dt    = (const float*)d_in[6];
    const float* A_log   = (const float*)d_in[7];
    const float* Dskip   = (const float*)d_in[8];
    const float* W_out   = (const float*)d_in[9];
    const float* nin_w   = (const float*)d_in[10];
    const float* fuse_W  = (const float*)d_in[11];
    const float* fuse_b  = (const float*)d_in[12];
    const float* ff_W1   = (const float*)d_in[13];
    const float* ff_W2   = (const float*)d_in[14];
    const float* nout_w  = (const float*)d_in[15];
    float* out = (float*)d_out;

    __nv_bfloat16* p_h    = sym_addr<__nv_bfloat16>(g_h_b);
    float*         p_xz   = sym_addr<float>(g_xz);
    __nv_bfloat16* p_u    = sym_addr<__nv_bfloat16>(g_u_b);
    __nv_bfloat16* p_xdbl = sym_addr<__nv_bfloat16>(g_xdbl_b);
    float*         p_dt   = sym_addr<float>(g_dt);
    __nv_bfloat16* p_gate = sym_addr<__nv_bfloat16>(g_gate_b);
    __nv_bfloat16* p_hcat = sym_addr<__nv_bfloat16>(g_hcat_b);
    float*         p_uv   = sym_addr<float>(g_uv);
    __nv_bfloat16* p_h2   = sym_addr<__nv_bfloat16>(g_h2_b);
    __nv_bfloat16* p_ff1  = sym_addr<__nv_bfloat16>(g_ff1_b);
    float*         p_ff2  = sym_addr<float>(g_ff2);
    __nv_bfloat16* p_Win  = sym_addr<__nv_bfloat16>(g_Win_b);
    __nv_bfloat16* p_Wcat = sym_addr<__nv_bfloat16>(g_Wcat_b);
    __nv_bfloat16* p_Wout = sym_addr<__nv_bfloat16>(g_Wout_b);
    __nv_bfloat16* p_Wfu  = sym_addr<__nv_bfloat16>(g_fuse_b);
    __nv_bfloat16* p_Wf1  = sym_addr<__nv_bfloat16>(g_ff1w_b);
    __nv_bfloat16* p_Wf2  = sym_addr<__nv_bfloat16>(g_ff2w_b);

    cudaFuncSetAttribute(tc_gemm<0,float>,         cudaFuncAttributeMaxDynamicSharedMemorySize, GEMM_SMEM);
    cudaFuncSetAttribute(tc_gemm<4,float>,         cudaFuncAttributeMaxDynamicSharedMemorySize, GEMM_SMEM);
    cudaFuncSetAttribute(tc_gemm<3,float>,         cudaFuncAttributeMaxDynamicSharedMemorySize, GEMM_SMEM);
    cudaFuncSetAttribute(tc_gemm<0,__nv_bfloat16>, cudaFuncAttributeMaxDynamicSharedMemorySize, GEMM_SMEM);
    cudaFuncSetAttribute(tc_gemm<1,__nv_bfloat16>, cudaFuncAttributeMaxDynamicSharedMemorySize, GEMM_SMEM);
    cudaFuncSetAttribute(scan_kernel,              cudaFuncAttributeMaxDynamicSharedMemorySize, SCAN_SMEM);

    dim3 blk(256);

    // 1. weight conversions + wcomb (single launch)
    convert_all<<<(NV_TOT+255)/256, blk>>>(W_in, W_xproj, W_out, fuse_W, ff_W1, ff_W2, W_dt);

    // 2. h = rmsnorm(x) -> bf16
    rmsnorm_kernel<__nv_bfloat16><<<ROWS, 128>>>(x, nullptr, nin_w, p_h);

    // 3. xz = h @ W_in^T   (N=2048, K=512) -> fp32
    tc_gemm<0,float><<<dim3(16,16), blk, GEMM_SMEM>>>(p_h, p_Win, nullptr, p_xz, 2*DINNER, DMODEL,
                                                      0, 0, nullptr, 0);

    // 4. conv + silu, both directions -> bf16
    conv_kernel<<<(ROWS*DINNER)/256, blk>>>(conv_w, conv_b);

    // 5. [dt | BC] = u @ Wcat^T  (N=1152, K=1024), both directions via blockIdx.z; BC -> bf16 interleaved
    tc_gemm<4,float><<<dim3(9,16,2), blk, GEMM_SMEM>>>(p_u, p_Wcat, b_dt,
                                                       p_dt, DINNER, DINNER,
                                                       (size_t)ROWS*DINNER, (size_t)ROWS*DINNER,
                                                       p_xdbl, (size_t)ROWS*128);

    // 6. selective scan -> gate bf16
    scan_kernel<<<dim3(64, BATCH, 2), 512, SCAN_SMEM>>>(A_log, Dskip);

    // 7. hcat[:, dir*512:] = gate @ W_out^T (N=512, K=1024), both dirs via z
    tc_gemm<0,__nv_bfloat16><<<dim3(4,16,2), blk, GEMM_SMEM>>>(p_gate, p_Wout, nullptr,
                                                               p_hcat, 2*DMODEL, DINNER,
                                                               (size_t)ROWS*DINNER, (size_t)DMODEL,
                                                               nullptr, 0);

    // 8. uv = hcat @ fuse_W^T + fuse_b  (N=1024, K=1024) -> fp32
    tc_gemm<3,float><<<dim3(8,16), blk, GEMM_SMEM>>>(p_hcat, p_Wfu, fuse_b, p_uv, 2*DMODEL, 2*DMODEL,
                                                     0, 0, nullptr, 0);

    // 9. h2 = silu(ug * sigmoid(vg)) -> bf16
    glu_kernel<<<(ROWS*DMODEL)/256, blk>>>();

    // 10. ff1 = silu(h2 @ ff_W1^T)  (N=2048, K=512) -> bf16
    tc_gemm<1,__nv_bfloat16><<<dim3(16,16), blk, GEMM_SMEM>>>(p_h2, p_Wf1, nullptr, p_ff1, 4*DMODEL, DMODEL,
                                                              0, 0, nullptr, 0);

    // 11. ff2 = ff1 @ ff_W2^T  (N=512, K=2048) -> fp32
    tc_gemm<0,float><<<dim3(4,16), blk, GEMM_SMEM>>>(p_ff1, p_Wf2, nullptr, p_ff2, DMODEL, 4*DMODEL,
                                                     0, 0, nullptr, 0);

    // 12. out = rmsnorm(x + ff2)
    rmsnorm_kernel<float><<<ROWS, 128>>>(x, p_ff2, nout_w, out);
}

// round 15
// speedup vs baseline: 2.4881x; 1.1905x over previous
#include <cuda_runtime.h>
#include <cuda_bf16.h>
#include <math.h>
#include <stdint.h>

// ---------------- problem constants ----------------
#define BATCH   2
#define LSEQ    1024
#define DMODEL  512
#define DINNER  1024
#define DSTATE  64
#define DTRANK  32
#define ROWS    (BATCH*LSEQ)          // 2048
#define EPSV    1e-6f

// ---------------- scratch (device globals; no allocations allowed) ----------------
__device__ __align__(16) __nv_bfloat16 g_h_b   [ROWS*DMODEL];      // rmsnorm(x) bf16
__device__ __align__(16) float         g_xz    [ROWS*2*DINNER];    // h @ W_in^T (u | z) fp32
__device__ __align__(16) __nv_bfloat16 g_u_b   [2][ROWS*DINNER];   // conv+silu bf16
__device__ __align__(16) __nv_bfloat16 g_xdbl_b[2][ROWS*128];      // [B|C] bf16, pair-interleaved
__device__ __align__(16) float         g_dt    [2][ROWS*DINNER];   // softplus(dt) fp32
__device__ __align__(16) __nv_bfloat16 g_gate_b[2][ROWS*DINNER];   // (y+u*D)*silu(z) bf16
__device__ __align__(16) __nv_bfloat16 g_hcat_b[ROWS*2*DMODEL];    // [hf|hb] bf16
__device__ __align__(16) float         g_uv    [ROWS*2*DMODEL];    // fuse out fp32
__device__ __align__(16) __nv_bfloat16 g_h2_b  [ROWS*DMODEL];      // silu(glu) bf16
__device__ __align__(16) __nv_bfloat16 g_ff1_b [ROWS*4*DMODEL];    // silu(ff1) bf16
__device__ __align__(16) float         g_ff2   [ROWS*DMODEL];      // ff2 fp32
// bf16 weights
__device__ __align__(16) __nv_bfloat16 g_Win_b [2*DINNER*DMODEL];
__device__ __align__(16) __nv_bfloat16 g_Wcat_b[(DINNER+128)*DINNER]; // [Wcomb(1024) | Wxp(128)] rows
__device__ __align__(16) __nv_bfloat16 g_Wout_b[DMODEL*DINNER];
__device__ __align__(16) __nv_bfloat16 g_fuse_b[2*DMODEL*2*DMODEL];
__device__ __align__(16) __nv_bfloat16 g_ff1w_b[4*DMODEL*DMODEL];
__device__ __align__(16) __nv_bfloat16 g_ff2w_b[DMODEL*4*DMODEL];

// ---------------- math helpers ----------------
__device__ __forceinline__ float sigmoidf_(float x){ return 1.0f/(1.0f+expf(-x)); }
__device__ __forceinline__ float siluf_(float x){ return x/(1.0f+expf(-x)); }
__device__ __forceinline__ float softplusf_(float x){ return (x>20.0f)? x : log1pf(expf(x)); }

__device__ __forceinline__ uint32_t smem_u32_(const void* p){
    uint32_t a;
    asm("{ .reg .u64 t; cvta.to.shared.u64 t, %1; cvt.u32.u64 %0, t; }" : "=r"(a) : "l"(p));
    return a;
}

// ---------------- mma.sync bf16 GEMM: C[M,N] = A[M,K](bf16) @ W[N,K](bf16)^T ----------------
// EPI: 0 none, 1 silu, 3 +bias, 4 split(dt: softplus+bias | BC: none -> C2 bf16 interleaved)
#define KCHUNK  64
#define SROW    72
#define CHUNK_BYTES (128*SROW*2)          // 18432 per matrix per stage
#define NSTAGE  3
#define GEMM_SMEM (NSTAGE*2*CHUNK_BYTES)  // 110592

__device__ __forceinline__ void ldsm_x4(uint32_t& r0, uint32_t& r1, uint32_t& r2, uint32_t& r3, uint32_t a){
    asm volatile("ldmatrix.sync.aligned.m8n8.x4.shared.b16 {%0,%1,%2,%3},[%4];"
                 : "=r"(r0),"=r"(r1),"=r"(r2),"=r"(r3) : "r"(a));
}
__device__ __forceinline__ void ldsm_x2(uint32_t& r0, uint32_t& r1, uint32_t a){
    asm volatile("ldmatrix.sync.aligned.m8n8.x2.shared.b16 {%0,%1},[%2];"
                 : "=r"(r0),"=r"(r1) : "r"(a));
}
__device__ __forceinline__ void mma16816(float* d, const uint32_t* a, const uint32_t* b){
    asm volatile("mma.sync.aligned.m16n8k16.row.col.f32.bf16.bf16.f32 "
                 "{%0,%1,%2,%3},{%4,%5,%6,%7},{%8,%9},{%0,%1,%2,%3};"
                 : "+f"(d[0]),"+f"(d[1]),"+f"(d[2]),"+f"(d[3])
                 : "r"(a[0]),"r"(a[1]),"r"(a[2]),"r"(a[3]), "r"(b[0]),"r"(b[1]));
}

template<int EPI, typename OutT>
__global__ void __launch_bounds__(256, 2)
tc_gemm(const __nv_bfloat16* __restrict__ A,
        const __nv_bfloat16* __restrict__ W,
        const float* __restrict__ bias,
        OutT* __restrict__ C, int ldc, int K,
        size_t zsA, size_t zsC,
        __nv_bfloat16* __restrict__ C2, size_t zsC2)
{
    extern __shared__ char smem[];
    uint32_t sb = smem_u32_(smem);
    int tid = threadIdx.x, lane = tid & 31, w = tid >> 5;
    int wm = w >> 2, wn = w & 3;              // 2 x 4 warp grid
    int m0 = blockIdx.y*128, n0 = blockIdx.x*128;

    A += (size_t)blockIdx.z * zsA;
    C += (size_t)blockIdx.z * zsC;
    if (EPI==4) C2 += (size_t)blockIdx.z * zsC2;

    const __nv_bfloat16* Abase = A + (size_t)m0*K;
    const __nv_bfloat16* Wbase = W + (size_t)n0*K;
    const int NC = K / KCHUNK;

    auto load_chunk = [&](int c, int s){
        uint32_t abuf = sb + (uint32_t)s*2*CHUNK_BYTES;
        uint32_t bbuf = abuf + CHUNK_BYTES;
        const __nv_bfloat16* Ag = Abase + c*KCHUNK;
        const __nv_bfloat16* Wg = Wbase + c*KCHUNK;
        #pragma unroll
        for (int i=0;i<4;i++){
            int idx = i*256 + tid;            // 0..1023
            int r = idx>>3, cc = idx&7;
            uint32_t dst = (uint32_t)(r*(SROW*2) + cc*16);
            asm volatile("cp.async.cg.shared.global [%0],[%1],16;"
                         :: "r"(abuf+dst), "l"((const void*)(Ag + (size_t)r*K + cc*8)));
            asm volatile("cp.async.cg.shared.global [%0],[%1],16;"
                         :: "r"(bbuf+dst), "l"((const void*)(Wg + (size_t)r*K + cc*8)));
        }
        asm volatile("cp.async.commit_group;");
    };

    float acc[4][4][4];
    #pragma unroll
    for (int i=0;i<4;i++)
        #pragma unroll
        for (int j=0;j<4;j++)
            #pragma unroll
            for (int q=0;q<4;q++) acc[i][j][q]=0.f;

    int a_row  = wm*64 + (lane & 15);
    int a_koff = (lane >> 4) * 8;
    int b_row  = wn*32 + (lane & 7);
    int b_koff = ((lane >> 3) & 1) * 8;

    load_chunk(0,0);
    if (NC>1) load_chunk(1,1);

    for (int c=0;c<NC;c++){
        int s = c % NSTAGE;
        if (c+1<NC) asm volatile("cp.async.wait_group 1;" ::: "memory");
        else        asm volatile("cp.async.wait_group 0;" ::: "memory");
        __syncthreads();
        if (c+2<NC) load_chunk(c+2, (c+2)%NSTAGE);
        uint32_t abuf = sb + (uint32_t)s*2*CHUNK_BYTES;
        uint32_t bbuf = abuf + CHUNK_BYTES;
        #pragma unroll
        for (int ks=0; ks<KCHUNK/16; ks++){
            uint32_t afr[4][4], bfr[4][2];
            #pragma unroll
            for (int mt=0;mt<4;mt++){
                uint32_t addr = abuf + (uint32_t)(((a_row + mt*16)*SROW + ks*16 + a_koff)*2);
                ldsm_x4(afr[mt][0],afr[mt][1],afr[mt][2],afr[mt][3], addr);
            }
            #pragma unroll
            for (int nt=0;nt<4;nt++){
                uint32_t addr = bbuf + (uint32_t)(((b_row + nt*8)*SROW + ks*16 + b_koff)*2);
                ldsm_x2(bfr[nt][0],bfr[nt][1], addr);
            }
            #pragma unroll
            for (int mt=0;mt<4;mt++)
                #pragma unroll
                for (int nt=0;nt<4;nt++)
                    mma16816(acc[mt][nt], afr[mt], bfr[nt]);
        }
    }

    // epilogue
    bool bc_side = (EPI==4) && (n0 >= DINNER);  // BC columns -> C2 (bf16, pair-interleaved)

    int rbase = m0 + wm*64 + (lane>>2);
    int cbase = n0 + wn*32 + (lane&3)*2;
    #pragma unroll
    for (int mt=0;mt<4;mt++){
        #pragma unroll
        for (int nt=0;nt<4;nt++){
            int col = cbase + nt*8;
            float v[4];
            #pragma unroll
            for (int q=0;q<4;q++){
                float x = acc[mt][nt][q];
                int cc = col + (q&1);
                if (EPI==1) x = siluf_(x);
                else if (EPI==3) x = x + bias[cc];
                else if (EPI==4){ if (!bc_side) x = softplusf_(x + bias[cc]); }
                v[q] = x;
            }
            int r0 = rbase + mt*16, r1 = r0 + 8;
            if (bc_side){
                // interleave: out col layout [B0 B1 C0 C1 B2 B3 C2 C3 ...]
                int oc = col - DINNER;       // even, 0..126
                int pos = (oc < 64) ? ((oc>>1)*4) : (((oc-64)>>1)*4 + 2);
                *(__nv_bfloat162*)(C2 + (size_t)r0*128 + pos) = __floats2bfloat162_rn(v[0],v[1]);
                *(__nv_bfloat162*)(C2 + (size_t)r1*128 + pos) = __floats2bfloat162_rn(v[2],v[3]);
            } else if (sizeof(OutT)==4){
                *(float2*)((float*)C + (size_t)r0*ldc + col) = make_float2(v[0],v[1]);
                *(float2*)((float*)C + (size_t)r1*ldc + col) = make_float2(v[2],v[3]);
            } else {
                *(__nv_bfloat162*)((__nv_bfloat16*)C + (size_t)r0*ldc + col) = __floats2bfloat162_rn(v[0],v[1]);
                *(__nv_bfloat162*)((__nv_bfloat16*)C + (size_t)r1*ldc + col) = __floats2bfloat162_rn(v[2],v[3]);
            }
        }
    }
}

// ---------------- rmsnorm ----------------
template<typename OutT>
__global__ void rmsnorm_kernel(const float* __restrict__ x,
                               const float* __restrict__ addsrc,
                               const float* __restrict__ w,
                               OutT* __restrict__ out)
{
    int row = blockIdx.x;
    int t = threadIdx.x;
    const float4* x4 = (const float4*)(x + (size_t)row*DMODEL);
    float4 v = x4[t];
    if (addsrc){
        const float4* a4 = (const float4*)(addsrc + (size_t)row*DMODEL);
        float4 a = a4[t];
        v.x+=a.x; v.y+=a.y; v.z+=a.z; v.w+=a.w;
    }
    float ss = v.x*v.x + v.y*v.y + v.z*v.z + v.w*v.w;
    #pragma unroll
    for (int o=16;o;o>>=1) ss += __shfl_xor_sync(0xffffffffu, ss, o);
    __shared__ float sacc[4];
    if ((t&31)==0) sacc[t>>5] = ss;
    __syncthreads();
    float tot = sacc[0]+sacc[1]+sacc[2]+sacc[3];
    float rinv = rsqrtf(tot*(1.0f/(float)DMODEL) + EPSV);
    const float4* w4 = (const float4*)w;
    float4 wv = w4[t];
    float o0=v.x*rinv*wv.x, o1=v.y*rinv*wv.y, o2=v.z*rinv*wv.z, o3=v.w*rinv*wv.w;
    OutT* op = out + (size_t)row*DMODEL + t*4;
    op[0]=(OutT)o0; op[1]=(OutT)o1; op[2]=(OutT)o2; op[3]=(OutT)o3;
}

// ---------------- single-kernel weight conversion + wcomb (merged) ----------------
#define NV_WIN  (2*DINNER*DMODEL/4)     // 262144
#define NV_WXP  (128*DINNER/4)          // 32768
#define NV_WOUT (DMODEL*DINNER/4)       // 131072
#define NV_FUSE (4*DMODEL*DMODEL/4)     // 262144
#define NV_CVT  (NV_WIN+NV_WXP+NV_WOUT+3*NV_FUSE)
#define NV_WCB  (DINNER*DINNER/4)       // 262144 (vectorized wcomb)
#define NV_TOT  (NV_CVT+NV_WCB)

__device__ __forceinline__ void cvt4(const float* s, __nv_bfloat16* d, int i){
    float4 v = ((const float4*)s)[i];
    ((__nv_bfloat162*)d)[2*i  ] = __floats2bfloat162_rn(v.x, v.y);
    ((__nv_bfloat162*)d)[2*i+1] = __floats2bfloat162_rn(v.z, v.w);
}
__global__ void convert_all(const float* __restrict__ W_in,
                            const float* __restrict__ W_xproj,
                            const float* __restrict__ W_out,
                            const float* __restrict__ fuse_W,
                            const float* __restrict__ ff_W1,
                            const float* __restrict__ ff_W2,
                            const float* __restrict__ W_dt)
{
    int i = blockIdx.x*256 + threadIdx.x;
    if (i >= NV_TOT) return;
    if (i < NV_WIN){ cvt4(W_in, g_Win_b, i); return; }
    i -= NV_WIN;
    if (i < NV_WXP){ cvt4(W_xproj + DTRANK*DINNER, g_Wcat_b + DINNER*DINNER, i); return; }
    i -= NV_WXP;
    if (i < NV_WOUT){ cvt4(W_out, g_Wout_b, i); return; }
    i -= NV_WOUT;
    if (i < NV_FUSE){ cvt4(fuse_W, g_fuse_b, i); return; }
    i -= NV_FUSE;
    if (i < NV_FUSE){ cvt4(ff_W1, g_ff1w_b, i); return; }
    i -= NV_FUSE;
    if (i < NV_FUSE){ cvt4(ff_W2, g_ff2w_b, i); return; }
    i -= NV_FUSE;
    // wcomb: W_comb[i4] = W_dt[r_i,:32] @ W_xproj[:32, j4..j4+3]
    {
        int ri = i >> 8;                 // output row 0..1023
        int j4 = (i & 255) * 4;          // output col group
        float4 s = make_float4(0.f,0.f,0.f,0.f);
        #pragma unroll
        for (int r=0;r<32;r++){
            float wd = W_dt[ri*32 + r];
            float4 wx = *(const float4*)&W_xproj[r*DINNER + j4];
            s.x = fmaf(wd, wx.x, s.x); s.y = fmaf(wd, wx.y, s.y);
            s.z = fmaf(wd, wx.z, s.z); s.w = fmaf(wd, wx.w, s.w);
        }
        __nv_bfloat162* dst = (__nv_bfloat162*)&g_Wcat_b[ri*DINNER + j4];
        dst[0] = __floats2bfloat162_rn(s.x, s.y);
        dst[1] = __floats2bfloat162_rn(s.z, s.w);
    }
}

// ---------------- depthwise causal conv (both directions) + bias + silu -> bf16 ----------------
__global__ void conv_kernel(const float* __restrict__ cw, const float* __restrict__ cb)
{
    int idx = blockIdx.x*256 + threadIdx.x;
    if (idx >= ROWS*DINNER) return;
    int d = idx & (DINNER-1);
    int r = idx >> 10;
    int l = r & (LSEQ-1);
    int b = r >> 10;
    float w0=cw[d*4+0], w1=cw[d*4+1], w2=cw[d*4+2], w3=cw[d*4+3];
    float bias = cb[d];
    const float* up = g_xz + (size_t)(b<<10)*(2*DINNER) + d;
    auto U = [&](int li)->float{ return (li>=0 && li<LSEQ) ? up[(size_t)li*(2*DINNER)] : 0.0f; };
    float um3=U(l-3), um2=U(l-2), um1=U(l-1), u0=U(l), up1=U(l+1), up2=U(l+2), up3=U(l+3);
    float f  = bias + w0*um3 + w1*um2 + w2*um1 + w3*u0;
    float bw = bias + w3*u0  + w2*up1 + w1*up2 + w0*up3;
    g_u_b[0][idx] = __float2bfloat16(siluf_(f));
    g_u_b[1][idx] = __float2bfloat16(siluf_(bw));
}

// ---------------- selective scan v5: one warp = 2 channels; shared B/C; 32-way reduce-scatter ----------------
#define SCAN_T 64
#define SCAN_SMEM (2*SCAN_T*128*2)   // 32768 bytes (bf16)
#define L2E 1.4426950408889634f

template<int DIR>
__device__ __forceinline__ void scan_body(const float* __restrict__ A_log,
                                          const float* __restrict__ Dskip,
                                          __nv_bfloat16* sBC)
{
    constexpr intptr_t STR  = DIR ? -(intptr_t)DINNER : (intptr_t)DINNER;
    constexpr intptr_t STRZ = 2*STR;
    int tid  = threadIdx.x;
    int warp = tid >> 5, lane = tid & 31;
    int b    = blockIdx.y;
    int d0   = (blockIdx.x*16 + warp)*2;     // channel pair (d0, d0+1)
    int n0   = lane*2;

    // exp2-folded A constants per chain (A_log is broadcast over d, but load per chain for safety)
    float a00 = -expf(A_log[(d0  )*DSTATE + n0    ]) * L2E;
    float a01 = -expf(A_log[(d0  )*DSTATE + n0 + 1]) * L2E;
    float a10 = -expf(A_log[(d0+1)*DSTATE + n0    ]) * L2E;
    float a11 = -expf(A_log[(d0+1)*DSTATE + n0 + 1]) * L2E;
    float dsk0 = Dskip[d0], dsk1 = Dskip[d0+1];
    float s00=0.f, s01=0.f, s10=0.f, s11=0.f;

    const __nv_bfloat16* xd = g_xdbl_b[DIR];
    uint32_t sbase = smem_u32_(sBC);

    auto stage = [&](int cc, int buf){
        int row0 = (b<<10) + (DIR ? (960 - cc*SCAN_T) : cc*SCAN_T);
        const __nv_bfloat16* src = xd + (size_t)row0*128;
        uint32_t dstb = sbase + (uint32_t)buf*(SCAN_T*128*2);
        #pragma unroll
        for (int i=0;i<2;i++){
            int idx = i*512 + tid;                 // 16B block index
            asm volatile("cp.async.cg.shared.global [%0],[%1],16;"
                         :: "r"(dstb + idx*16), "l"((const void*)(src + idx*8)));
        }
        asm volatile("cp.async.commit_group;");
    };

    stage(0,0);

    for (int cc=0; cc<LSEQ/SCAN_T; cc++){
        asm volatile("cp.async.wait_group 0;" ::: "memory");
        __syncthreads();
        if (cc+1 < LSEQ/SCAN_T) stage(cc+1, (cc+1)&1);

        const __nv_bfloat16* bcb = sBC + (cc&1)*(SCAN_T*128);
        size_t gr = (size_t)(b<<10) + (DIR ? (1023 - cc*SCAN_T) : cc*SCAN_T);
        const float* dtP = g_dt[DIR] + gr*DINNER + d0;
        const __nv_bfloat16* uP = g_u_b[DIR] + gr*DINNER + d0;
        const float* zP  = g_xz + gr*(2*DINNER) + DINNER + d0;
        __nv_bfloat16* gP = g_gate_b[DIR] + gr*DINNER + d0;

        #pragma unroll 1
        for (int jj=0; jj<SCAN_T; jj+=16){
            float w[32];
            #pragma unroll
            for (int k=0;k<16;k++){
                int lt = jj + k;
                int j  = DIR ? (SCAN_T-1-lt) : lt;
                uint2 bc = *(const uint2*)(bcb + j*128 + lane*4);   // [B0 B1 C0 C1]
                float2 Bv = __bfloat1622float2(*(__nv_bfloat162*)&bc.x);
                float2 Cv = __bfloat1622float2(*(__nv_bfloat162*)&bc.y);
                float2 dt2 = __ldg((const float2*)(dtP + (intptr_t)lt*STR));
                float2 u2  = __bfloat1622float2(*(const __nv_bfloat162*)(uP + (intptr_t)lt*STR));
                // chain 0
                float dA00 = exp2f(dt2.x*a00);
                float dA01 = exp2f(dt2.x*a01);
                float dtu0 = dt2.x*u2.x;
                s00 = fmaf(s00, dA00, dtu0*Bv.x);
                s01 = fmaf(s01, dA01, dtu0*Bv.y);
                w[k] = s00*Cv.x + s01*Cv.y;
                // chain 1
                float dA10 = exp2f(dt2.y*a10);
                float dA11 = exp2f(dt2.y*a11);
                float dtu1 = dt2.y*u2.y;
                s10 = fmaf(s10, dA10, dtu1*Bv.x);
                s11 = fmaf(s11, dA11, dtu1*Bv.y);
                w[16+k] = s10*Cv.x + s11*Cv.y;
            }
            // 5-level reduce-scatter of 32 sums over 32 lanes: lane l ends owning index j=l
            float v16[16];
            #pragma unroll
            for (int k=0;k<16;k++){
                float keep = (lane&16)? w[k+16] : w[k];
                float send = (lane&16)? w[k] : w[k+16];
                v16[k] = keep + __shfl_xor_sync(0xffffffffu, send, 16);
            }
            float v8[8];
            #pragma unroll
            for (int k=0;k<8;k++){
                float keep = (lane&8)? v16[k+8] : v16[k];
                float send = (lane&8)? v16[k] : v16[k+8];
                v8[k] = keep + __shfl_xor_sync(0xffffffffu, send, 8);
            }
            float v4a[4];
            #pragma unroll
            for (int k=0;k<4;k++){
                float keep = (lane&4)? v8[k+4] : v8[k];
                float send = (lane&4)? v8[k] : v8[k+4];
                v4a[k] = keep + __shfl_xor_sync(0xffffffffu, send, 4);
            }
            float v2[2];
            #pragma unroll
            for (int k=0;k<2;k++){
                float keep = (lane&2)? v4a[k+2] : v4a[k];
                float send = (lane&2)? v4a[k] : v4a[k+2];
                v2[k] = keep + __shfl_xor_sync(0xffffffffu, send, 2);
            }
            float keep1 = (lane&1)? v2[1] : v2[0];
            float send1 = (lane&1)? v2[0] : v2[1];
            float q = keep1 + __shfl_xor_sync(0xffffffffu, send1, 1);

            // lane owns (chain = lane>>4, step = lane&15)
            {
                int ch = lane >> 4;
                int st = lane & 15;
                int lt = jj + st;
                float uu = __bfloat162float(__ldg(uP + (intptr_t)lt*STR + ch));
                float z  = __ldg(zP + (intptr_t)lt*STRZ + ch);
                float dskv = ch ? dsk1 : dsk0;
                float y = q + uu*dskv;
                gP[(intptr_t)lt*STR + ch] = __float2bfloat16(y * (z/(1.0f+__expf(-z))));
            }
        }
        __syncthreads();
    }
}

__global__ void __launch_bounds__(512)
scan_kernel(const float* __restrict__ A_log, const float* __restrict__ Dskip)
{
    extern __shared__ __nv_bfloat16 sBC[];
    if (blockIdx.z == 0) scan_body<0>(A_log, Dskip, sBC);
    else                 scan_body<1>(A_log, Dskip, sBC);
}

// ---------------- GLU gate + silu -> bf16 ----------------
__global__ void glu_kernel()
{
    int idx = blockIdx.x*256 + threadIdx.x;
    if (idx >= ROWS*DMODEL) return;
    int r = idx >> 9;
    int d = idx & (DMODEL-1);
    float ug = g_uv[(size_t)r*(2*DMODEL) + d];
    float vg = g_uv[(size_t)r*(2*DMODEL) + DMODEL + d];
    float h  = ug * sigmoidf_(vg);
    g_h2_b[idx] = __float2bfloat16(siluf_(h));
}

// ---------------- host side ----------------
template<typename T>
static T* sym_addr(const void* sym)
{
    void* p = nullptr;
    cudaGetSymbolAddress(&p, sym);
    return (T*)p;
}

extern "C" void kernel_launch(void* const* d_in, const int* in_sizes, int n_in,
                              void* d_out, int out_size)
{
    const float* x       = (const float*)d_in[0];
    const float* W_in    = (const float*)d_in[1];
    const float* conv_w  = (const float*)d_in[2];
    const float* conv_b  = (const float*)d_in[3];
    const float* W_xproj = (const float*)d_in[4];
    const float* W_dt    = (const float*)d_in[5];
    const float* b_dt    = (const float*)d_in[6];
    const float* A_log   = (const float*)d_in[7];
    const float* Dskip   = (const float*)d_in[8];
    const float* W_out   = (const float*)d_in[9];
    const float* nin_w   = (const float*)d_in[10];
    const float* fuse_W  = (const float*)d_in[11];
    const float* fuse_b  = (const float*)d_in[12];
    const float* ff_W1   = (const float*)d_in[13];
    const float* ff_W2   = (const float*)d_in[14];
    const float* nout_w  = (const float*)d_in[15];
    float* out = (float*)d_out;

    __nv_bfloat16* p_h    = sym_addr<__nv_bfloat16>(g_h_b);
    float*         p_xz   = sym_addr<float>(g_xz);
    __nv_bfloat16* p_u    = sym_addr<__nv_bfloat16>(g_u_b);
    __nv_bfloat16* p_xdbl = sym_addr<__nv_bfloat16>(g_xdbl_b);
    float*         p_dt   = sym_addr<float>(g_dt);
    __nv_bfloat16* p_gate = sym_addr<__nv_bfloat16>(g_gate_b);
    __nv_bfloat16* p_hcat = sym_addr<__nv_bfloat16>(g_hcat_b);
    float*         p_uv   = sym_addr<float>(g_uv);
    __nv_bfloat16* p_h2   = sym_addr<__nv_bfloat16>(g_h2_b);
    __nv_bfloat16* p_ff1  = sym_addr<__nv_bfloat16>(g_ff1_b);
    float*         p_ff2  = sym_addr<float>(g_ff2);
    __nv_bfloat16* p_Win  = sym_addr<__nv_bfloat16>(g_Win_b);
    __nv_bfloat16* p_Wcat = sym_addr<__nv_bfloat16>(g_Wcat_b);
    __nv_bfloat16* p_Wout = sym_addr<__nv_bfloat16>(g_Wout_b);
    __nv_bfloat16* p_Wfu  = sym_addr<__nv_bfloat16>(g_fuse_b);
    __nv_bfloat16* p_Wf1  = sym_addr<__nv_bfloat16>(g_ff1w_b);
    __nv_bfloat16* p_Wf2  = sym_addr<__nv_bfloat16>(g_ff2w_b);

    cudaFuncSetAttribute(tc_gemm<0,float>,         cudaFuncAttributeMaxDynamicSharedMemorySize, GEMM_SMEM);
    cudaFuncSetAttribute(tc_gemm<4,float>,         cudaFuncAttributeMaxDynamicSharedMemorySize, GEMM_SMEM);
    cudaFuncSetAttribute(tc_gemm<3,float>,         cudaFuncAttributeMaxDynamicSharedMemorySize, GEMM_SMEM);
    cudaFuncSetAttribute(tc_gemm<0,__nv_bfloat16>, cudaFuncAttributeMaxDynamicSharedMemorySize, GEMM_SMEM);
    cudaFuncSetAttribute(tc_gemm<1,__nv_bfloat16>, cudaFuncAttributeMaxDynamicSharedMemorySize, GEMM_SMEM);
    cudaFuncSetAttribute(scan_kernel,              cudaFuncAttributeMaxDynamicSharedMemorySize, SCAN_SMEM);

    dim3 blk(256);

    // 1. weight conversions + wcomb (single launch)
    convert_all<<<(NV_TOT+255)/256, blk>>>(W_in, W_xproj, W_out, fuse_W, ff_W1, ff_W2, W_dt);

    // 2. h = rmsnorm(x) -> bf16
    rmsnorm_kernel<__nv_bfloat16><<<ROWS, 128>>>(x, nullptr, nin_w, p_h);

    // 3. xz = h @ W_in^T   (N=2048, K=512) -> fp32
    tc_gemm<0,float><<<dim3(16,16), blk, GEMM_SMEM>>>(p_h, p_Win, nullptr, p_xz, 2*DINNER, DMODEL,
                                                      0, 0, nullptr, 0);

    // 4. conv + silu, both directions -> bf16
    conv_kernel<<<(ROWS*DINNER)/256, blk>>>(conv_w, conv_b);

    // 5. [dt | BC] = u @ Wcat^T  (N=1152, K=1024), both directions via blockIdx.z; BC -> bf16 interleaved
    tc_gemm<4,float><<<dim3(9,16,2), blk, GEMM_SMEM>>>(p_u, p_Wcat, b_dt,
                                                       p_dt, DINNER, DINNER,
                                                       (size_t)ROWS*DINNER, (size_t)ROWS*DINNER,
                                                       p_xdbl, (size_t)ROWS*128);

    // 6. selective scan -> gate bf16
    scan_kernel<<<dim3(32, BATCH, 2), 512, SCAN_SMEM>>>(A_log, Dskip);

    // 7. hcat[:, dir*512:] = gate @ W_out^T (N=512, K=1024), both dirs via z
    tc_gemm<0,__nv_bfloat16><<<dim3(4,16,2), blk, GEMM_SMEM>>>(p_gate, p_Wout, nullptr,
                                                               p_hcat, 2*DMODEL, DINNER,
                                                               (size_t)ROWS*DINNER, (size_t)DMODEL,
                                                               nullptr, 0);

    // 8. uv = hcat @ fuse_W^T + fuse_b  (N=1024, K=1024) -> fp32
    tc_gemm<3,float><<<dim3(8,16), blk, GEMM_SMEM>>>(p_hcat, p_Wfu, fuse_b, p_uv, 2*DMODEL, 2*DMODEL,
                                                     0, 0, nullptr, 0);

    // 9. h2 = silu(ug * sigmoid(vg)) -> bf16
    glu_kernel<<<(ROWS*DMODEL)/256, blk>>>();

    // 10. ff1 = silu(h2 @ ff_W1^T)  (N=2048, K=512) -> bf16
    tc_gemm<1,__nv_bfloat16><<<dim3(16,16), blk, GEMM_SMEM>>>(p_h2, p_Wf1, nullptr, p_ff1, 4*DMODEL, DMODEL,
                                                              0, 0, nullptr, 0);

    // 11. ff2 = ff1 @ ff_W2^T  (N=512, K=2048) -> fp32
    tc_gemm<0,float><<<dim3(4,16), blk, GEMM_SMEM>>>(p_ff1, p_Wf2, nullptr, p_ff2, DMODEL, 4*DMODEL,
                                                     0, 0, nullptr, 0);

    // 12. out = rmsnorm(x + ff2)
    rmsnorm_kernel<float><<<ROWS, 128>>>(x, p_ff2, nout_w, out);
}